// round 9
// baseline (speedup 1.0000x reference)
#include <cuda_runtime.h>
#include <cuda_fp16.h>
#include <cstdint>

#define DDIM   128
#define KPROTO 1024
#define NMB    4096          // 65536/16 row-strips
#define THREADS 64
typedef unsigned int u32;
typedef unsigned long long ull;

// Fragment-layout operand storage (static device arrays; no allocation).
__device__ uint4 g_Ah[NMB * 8 * 32];    // A fp16 frags [mb][ks][lane] = {a0,a1,a2,a3}
__device__ uint4 g_B [64 * 8 * 32];     // 256 KB: B-hi frags [nbpair][ks][lane] = {b0E,b1E,b0O,b1O}
__device__ float g_la [KPROTO];         // -10*log2e*alpha - c*pi^2/4
__device__ float g_inv[KPROTO];         // 1/||mu_col||

// ---------------- helpers ----------------
__device__ __forceinline__ u32 pack_h2(float a, float b) {
    __half2 t;
    t.x = __float2half_rn(a);
    t.y = __float2half_rn(b);
    return *reinterpret_cast<u32*>(&t);
}
__device__ __forceinline__ ull pack2(float lo, float hi) {
    ull r; asm("mov.b64 %0, {%1, %2};" : "=l"(r) : "f"(lo), "f"(hi)); return r;
}
__device__ __forceinline__ void unpack2(ull v, float& lo, float& hi) {
    asm("mov.b64 {%0, %1}, %2;" : "=f"(lo), "=f"(hi) : "l"(v));
}
__device__ __forceinline__ ull fma2(ull a, ull b, ull c) {
    ull d; asm("fma.rn.f32x2 %0, %1, %2, %3;" : "=l"(d) : "l"(a), "l"(b), "l"(c)); return d;
}
__device__ __forceinline__ ull mul2(ull a, ull b) {
    ull d; asm("mul.rn.f32x2 %0, %1, %2;" : "=l"(d) : "l"(a), "l"(b)); return d;
}
__device__ __forceinline__ float ex2(float x) {
    float r; asm("ex2.approx.f32 %0, %1;" : "=f"(r) : "f"(x)); return r;
}
__device__ __forceinline__ void mma16816h(float& d0, float& d1, float& d2, float& d3,
                                          u32 a0, u32 a1, u32 a2, u32 a3,
                                          u32 b0, u32 b1) {
    asm volatile(
        "mma.sync.aligned.m16n8k16.row.col.f32.f16.f16.f32 "
        "{%0,%1,%2,%3},{%4,%5,%6,%7},{%8,%9},{%0,%1,%2,%3};"
        : "+f"(d0), "+f"(d1), "+f"(d2), "+f"(d3)
        : "r"(a0), "r"(a1), "r"(a2), "r"(a3), "r"(b0), "r"(b1));
}

// ---------------- prep 1: column norms + folded alpha const ----------------
// exponent(p) = -c*p^2 + c*pi*p + la', with la' = -10*log2e*alpha - c*pi^2/4,
// where p = asin(ip), c = 5*log2(e).
__global__ void prep1(const float* __restrict__ mus, const float* __restrict__ alphas) {
    int n = blockIdx.x * blockDim.x + threadIdx.x;
    if (n >= KPROTO) return;
    float s = 0.0f;
#pragma unroll 8
    for (int d = 0; d < DDIM; d++) {
        float v = mus[d * KPROTO + n];
        s = fmaf(v, v, s);
    }
    g_inv[n] = rsqrtf(s);
    g_la[n]  = fmaf(-14.4269504088896340f, alphas[n], -17.7985387f);
}

// ---------------- prep 2: B-hi fragments, packed per nb-pair ----------------
__global__ void prep2(const float* __restrict__ mus) {
    int gid  = blockIdx.x * blockDim.x + threadIdx.x;   // 16384 threads
    int lane = gid & 31;
    int f    = gid >> 5;            // 0..511 = nbpair*8 + ks
    int np   = f >> 3;              // nb pair index (covers nb=2np, 2np+1)
    int ks   = f & 7;
    int g    = lane >> 2;
    int t4   = lane & 3;
    int k0   = ks * 16 + 2 * t4;
    int nE   = (2 * np) * 8 + g;
    int nO   = nE + 8;
    float iE = g_inv[nE], iO = g_inv[nO];
    float e0 = mus[(k0 + 0) * KPROTO + nE] * iE;
    float e1 = mus[(k0 + 1) * KPROTO + nE] * iE;
    float e2 = mus[(k0 + 8) * KPROTO + nE] * iE;
    float e3 = mus[(k0 + 9) * KPROTO + nE] * iE;
    float o0 = mus[(k0 + 0) * KPROTO + nO] * iO;
    float o1 = mus[(k0 + 1) * KPROTO + nO] * iO;
    float o2 = mus[(k0 + 8) * KPROTO + nO] * iO;
    float o3 = mus[(k0 + 9) * KPROTO + nO] * iO;
    uint4 o;
    o.x = pack_h2(e0, e1);   // nbE b0
    o.y = pack_h2(e2, e3);   // nbE b1
    o.z = pack_h2(o0, o1);   // nbO b0
    o.w = pack_h2(o2, o3);   // nbO b1
    g_B[f * 32 + lane] = o;
}

// ---------------- prep 3: A fragments (fp16 hi) ----------------
__global__ void prepA(const float* __restrict__ xs) {
    int tid  = threadIdx.x;
    int ks   = tid >> 5;
    int lane = tid & 31;
    int mb   = blockIdx.x;          // 0..4095
    int g    = lane >> 2;
    int t4   = lane & 3;
    int r0 = mb * 16 + g;
    int r1 = r0 + 8;
    int c0 = ks * 16 + 2 * t4;
    float2 p00 = *(const float2*)&xs[(size_t)r0 * DDIM + c0];
    float2 p01 = *(const float2*)&xs[(size_t)r0 * DDIM + c0 + 8];
    float2 p10 = *(const float2*)&xs[(size_t)r1 * DDIM + c0];
    float2 p11 = *(const float2*)&xs[(size_t)r1 * DDIM + c0 + 8];
    uint4 oh;
    oh.x = pack_h2(p00.x, p00.y);
    oh.y = pack_h2(p10.x, p10.y);
    oh.z = pack_h2(p01.x, p01.y);
    oh.w = pack_h2(p11.x, p11.y);
    g_Ah[((size_t)mb * 8 + ks) * 32 + lane] = oh;
}

// ---------------- main: single-product mma + asin-based epilogue ----------------
// Block = 64 threads = 2 warps; warp owns 2 strips (32 rows), iterates 64 nb-pairs.
// B fragments software-pipelined HALF AN ITERATION ahead in registers:
// load->use distance ~16 HMMAs + epilogue, hiding L1/L2 latency.
__global__ __launch_bounds__(THREADS, 7)
void main_kernel(float* __restrict__ out) {
    const int tid  = threadIdx.x;
    const int wid  = tid >> 5;
    const int lane = tid & 31;
    const int g    = lane >> 2;
    const int t4   = lane & 3;
    const int mb0  = blockIdx.x * 4 + wid * 2;   // first strip; second is mb0+1

    // A fragments for both strips: register-resident
    uint4 A0[8], A1[8];
    {
        const uint4* p0 = g_Ah + (size_t)mb0 * 256 + lane;
#pragma unroll
        for (int ks = 0; ks < 8; ks++) { A0[ks] = p0[ks * 32]; A1[ks] = p0[256 + ks * 32]; }
    }

    // asin Taylor (odd, deg 11) + exponent-fold constants
    const ull CA1 = pack2(0.16666667f,  0.16666667f);
    const ull CA2 = pack2(0.075f,       0.075f);
    const ull CA3 = pack2(0.044642857f, 0.044642857f);
    const ull CA4 = pack2(0.030381944f, 0.030381944f);
    const ull CA5 = pack2(0.022372159f, 0.022372159f);
    const ull NEGC = pack2(-7.2134752f, -7.2134752f);
    const ull CPI  = pack2(22.6618023f, 22.6618023f);

    // e(x0)+e(x1) for one packed pair with packed la
    auto tpair = [&](ull x2, ull la2) -> float {
        ull u  = mul2(x2, x2);
        ull q  = fma2(CA5, u, CA4);
        q = fma2(q, u, CA3);
        q = fma2(q, u, CA2);
        q = fma2(q, u, CA1);
        ull xu = mul2(x2, u);
        ull p  = fma2(xu, q, x2);     // asin(x)
        ull t  = fma2(p, NEGC, CPI);
        ull z  = fma2(p, t, la2);     // -c*p^2 + c*pi*p + la'
        float z0, z1; unpack2(z, z0, z1);
        return ex2(z0) + ex2(z1);
    };

    float s0 = 0.0f, s1 = 0.0f, s2 = 0.0f, s3 = 0.0f;
    const float2* la_p = (const float2*)g_la;

    ull ipp[8];            // prev iter packed ips
    ull lapE = 0, lapO = 0;

    // prime the B pipeline: ks0-3 of iteration 0
    uint4 Ba0, Ba1, Ba2, Ba3;    // current front half
    uint4 Bb0, Bb1, Bb2, Bb3;    // prefetched back half
    {
        const uint4* pB = g_B + lane;
        Ba0 = pB[0];  Ba1 = pB[32];  Ba2 = pB[64];  Ba3 = pB[96];
    }

#pragma unroll 1
    for (int it = 0; it < 64; it++) {
        const uint4* pB  = g_B + it * 256 + lane;
        const uint4* pBn = g_B + ((it + 1) & 63) * 256 + lane;   // wraps (redundant last iter)
        float2 laEf = la_p[(2 * it) * 4 + t4];
        float2 laOf = la_p[(2 * it + 1) * 4 + t4];

        float E00=0,E01=0,E02=0,E03=0;   // strip0 x nbE
        float E10=0,E11=0,E12=0,E13=0;   // strip1 x nbE
        float O00=0,O01=0,O02=0,O03=0;   // strip0 x nbO
        float O10=0,O11=0,O12=0,O13=0;   // strip1 x nbO

        // prefetch ks4-7 (used after the epilogue below)
        Bb0 = pB[128];  Bb1 = pB[160];  Bb2 = pB[192];  Bb3 = pB[224];

        // ks 0..3 from pre-staged registers
        {
            mma16816h(E00,E01,E02,E03, A0[0].x,A0[0].y,A0[0].z,A0[0].w, Ba0.x,Ba0.y);
            mma16816h(E10,E11,E12,E13, A1[0].x,A1[0].y,A1[0].z,A1[0].w, Ba0.x,Ba0.y);
            mma16816h(O00,O01,O02,O03, A0[0].x,A0[0].y,A0[0].z,A0[0].w, Ba0.z,Ba0.w);
            mma16816h(O10,O11,O12,O13, A1[0].x,A1[0].y,A1[0].z,A1[0].w, Ba0.z,Ba0.w);
            mma16816h(E00,E01,E02,E03, A0[1].x,A0[1].y,A0[1].z,A0[1].w, Ba1.x,Ba1.y);
            mma16816h(E10,E11,E12,E13, A1[1].x,A1[1].y,A1[1].z,A1[1].w, Ba1.x,Ba1.y);
            mma16816h(O00,O01,O02,O03, A0[1].x,A0[1].y,A0[1].z,A0[1].w, Ba1.z,Ba1.w);
            mma16816h(O10,O11,O12,O13, A1[1].x,A1[1].y,A1[1].z,A1[1].w, Ba1.z,Ba1.w);
            mma16816h(E00,E01,E02,E03, A0[2].x,A0[2].y,A0[2].z,A0[2].w, Ba2.x,Ba2.y);
            mma16816h(E10,E11,E12,E13, A1[2].x,A1[2].y,A1[2].z,A1[2].w, Ba2.x,Ba2.y);
            mma16816h(O00,O01,O02,O03, A0[2].x,A0[2].y,A0[2].z,A0[2].w, Ba2.z,Ba2.w);
            mma16816h(O10,O11,O12,O13, A1[2].x,A1[2].y,A1[2].z,A1[2].w, Ba2.z,Ba2.w);
            mma16816h(E00,E01,E02,E03, A0[3].x,A0[3].y,A0[3].z,A0[3].w, Ba3.x,Ba3.y);
            mma16816h(E10,E11,E12,E13, A1[3].x,A1[3].y,A1[3].z,A1[3].w, Ba3.x,Ba3.y);
            mma16816h(O00,O01,O02,O03, A0[3].x,A0[3].y,A0[3].z,A0[3].w, Ba3.z,Ba3.w);
            mma16816h(O10,O11,O12,O13, A1[3].x,A1[3].y,A1[3].z,A1[3].w, Ba3.z,Ba3.w);
        }

        // prev-iter epilogue, strip0 (overlaps MMAs + the Bb loads in flight)
        if (it > 0) {
            s0 += tpair(ipp[0], lapE) + tpair(ipp[2], lapO);
            s1 += tpair(ipp[1], lapE) + tpair(ipp[3], lapO);
        }

        // prefetch next iteration's ks0-3
        Ba0 = pBn[0];  Ba1 = pBn[32];  Ba2 = pBn[64];  Ba3 = pBn[96];

        // ks 4..7 from prefetched registers
        {
            mma16816h(E00,E01,E02,E03, A0[4].x,A0[4].y,A0[4].z,A0[4].w, Bb0.x,Bb0.y);
            mma16816h(E10,E11,E12,E13, A1[4].x,A1[4].y,A1[4].z,A1[4].w, Bb0.x,Bb0.y);
            mma16816h(O00,O01,O02,O03, A0[4].x,A0[4].y,A0[4].z,A0[4].w, Bb0.z,Bb0.w);
            mma16816h(O10,O11,O12,O13, A1[4].x,A1[4].y,A1[4].z,A1[4].w, Bb0.z,Bb0.w);
            mma16816h(E00,E01,E02,E03, A0[5].x,A0[5].y,A0[5].z,A0[5].w, Bb1.x,Bb1.y);
            mma16816h(E10,E11,E12,E13, A1[5].x,A1[5].y,A1[5].z,A1[5].w, Bb1.x,Bb1.y);
            mma16816h(O00,O01,O02,O03, A0[5].x,A0[5].y,A0[5].z,A0[5].w, Bb1.z,Bb1.w);
            mma16816h(O10,O11,O12,O13, A1[5].x,A1[5].y,A1[5].z,A1[5].w, Bb1.z,Bb1.w);
            mma16816h(E00,E01,E02,E03, A0[6].x,A0[6].y,A0[6].z,A0[6].w, Bb2.x,Bb2.y);
            mma16816h(E10,E11,E12,E13, A1[6].x,A1[6].y,A1[6].z,A1[6].w, Bb2.x,Bb2.y);
            mma16816h(O00,O01,O02,O03, A0[6].x,A0[6].y,A0[6].z,A0[6].w, Bb2.z,Bb2.w);
            mma16816h(O10,O11,O12,O13, A1[6].x,A1[6].y,A1[6].z,A1[6].w, Bb2.z,Bb2.w);
            mma16816h(E00,E01,E02,E03, A0[7].x,A0[7].y,A0[7].z,A0[7].w, Bb3.x,Bb3.y);
            mma16816h(E10,E11,E12,E13, A1[7].x,A1[7].y,A1[7].z,A1[7].w, Bb3.x,Bb3.y);
            mma16816h(O00,O01,O02,O03, A0[7].x,A0[7].y,A0[7].z,A0[7].w, Bb3.z,Bb3.w);
            mma16816h(O10,O11,O12,O13, A1[7].x,A1[7].y,A1[7].z,A1[7].w, Bb3.z,Bb3.w);
        }

        // prev-iter epilogue, strip1
        if (it > 0) {
            s2 += tpair(ipp[4], lapE) + tpair(ipp[6], lapO);
            s3 += tpair(ipp[5], lapE) + tpair(ipp[7], lapO);
        }

        ipp[0] = pack2(E00, E01);  ipp[1] = pack2(E02, E03);
        ipp[2] = pack2(O00, O01);  ipp[3] = pack2(O02, O03);
        ipp[4] = pack2(E10, E11);  ipp[5] = pack2(E12, E13);
        ipp[6] = pack2(O10, O11);  ipp[7] = pack2(O12, O13);
        lapE = pack2(laEf.x, laEf.y);
        lapO = pack2(laOf.x, laOf.y);
    }

    // drain pipeline
    s0 += tpair(ipp[0], lapE) + tpair(ipp[2], lapO);
    s1 += tpair(ipp[1], lapE) + tpair(ipp[3], lapO);
    s2 += tpair(ipp[4], lapE) + tpair(ipp[6], lapO);
    s3 += tpair(ipp[5], lapE) + tpair(ipp[7], lapO);

    // reduce across the 4 lanes sharing the same rows (t4 = 0..3)
    s0 += __shfl_xor_sync(0xffffffffu, s0, 1);
    s0 += __shfl_xor_sync(0xffffffffu, s0, 2);
    s1 += __shfl_xor_sync(0xffffffffu, s1, 1);
    s1 += __shfl_xor_sync(0xffffffffu, s1, 2);
    s2 += __shfl_xor_sync(0xffffffffu, s2, 1);
    s2 += __shfl_xor_sync(0xffffffffu, s2, 2);
    s3 += __shfl_xor_sync(0xffffffffu, s3, 1);
    s3 += __shfl_xor_sync(0xffffffffu, s3, 2);

    if (t4 == 0) {
        int r0 = mb0 * 16 + g;
        out[r0]      = 0.1f * log1pf(1.0f / s0);
        out[r0 + 8]  = 0.1f * log1pf(1.0f / s1);
        out[r0 + 16] = 0.1f * log1pf(1.0f / s2);
        out[r0 + 24] = 0.1f * log1pf(1.0f / s3);
    }
}

// ---------------- launch ----------------
extern "C" void kernel_launch(void* const* d_in, const int* in_sizes, int n_in,
                              void* d_out, int out_size) {
    const float* xs     = (const float*)d_in[0];
    const float* mus    = (const float*)d_in[1];
    const float* alphas = (const float*)d_in[2];
    float* out = (float*)d_out;

    int B = in_sizes[0] / DDIM;    // 65536

    prep1<<<(KPROTO + 255) / 256, 256>>>(mus, alphas);
    prep2<<<64, 256>>>(mus);
    prepA<<<B / 16, 256>>>(xs);
    main_kernel<<<B / 64, THREADS>>>(out);
}

// round 10
// speedup vs baseline: 1.1891x; 1.1891x over previous
#include <cuda_runtime.h>
#include <cuda_fp16.h>
#include <cstdint>

#define DDIM   128
#define KPROTO 1024
#define NMB    4096          // 65536/16 row-strips
typedef unsigned int u32;
typedef unsigned long long ull;

// Fragment-layout operand storage (static device arrays; no allocation).
__device__ uint4 g_Ah[NMB * 8 * 32];    // A fp16 frags [mb][ks][lane] = {a0,a1,a2,a3}
__device__ uint4 g_B [64 * 8 * 32];     // 256 KB: B-hi frags [nbpair][ks][lane] = {b0E,b1E,b0O,b1O}
__device__ float g_la [KPROTO];         // -10*log2e*alpha - c*pi^2/4
__device__ float g_inv[KPROTO];         // 1/||mu_col||
__device__ float g_S  [2 * 65536];      // per-half partial sums (deterministic, no atomics)

// ---------------- helpers ----------------
__device__ __forceinline__ u32 pack_h2(float a, float b) {
    __half2 t;
    t.x = __float2half_rn(a);
    t.y = __float2half_rn(b);
    return *reinterpret_cast<u32*>(&t);
}
__device__ __forceinline__ ull pack2(float lo, float hi) {
    ull r; asm("mov.b64 %0, {%1, %2};" : "=l"(r) : "f"(lo), "f"(hi)); return r;
}
__device__ __forceinline__ void unpack2(ull v, float& lo, float& hi) {
    asm("mov.b64 {%0, %1}, %2;" : "=f"(lo), "=f"(hi) : "l"(v));
}
__device__ __forceinline__ ull fma2(ull a, ull b, ull c) {
    ull d; asm("fma.rn.f32x2 %0, %1, %2, %3;" : "=l"(d) : "l"(a), "l"(b), "l"(c)); return d;
}
__device__ __forceinline__ ull mul2(ull a, ull b) {
    ull d; asm("mul.rn.f32x2 %0, %1, %2;" : "=l"(d) : "l"(a), "l"(b)); return d;
}
__device__ __forceinline__ float ex2(float x) {
    float r; asm("ex2.approx.f32 %0, %1;" : "=f"(r) : "f"(x)); return r;
}
__device__ __forceinline__ void mma16816h(float& d0, float& d1, float& d2, float& d3,
                                          u32 a0, u32 a1, u32 a2, u32 a3,
                                          u32 b0, u32 b1) {
    asm volatile(
        "mma.sync.aligned.m16n8k16.row.col.f32.f16.f16.f32 "
        "{%0,%1,%2,%3},{%4,%5,%6,%7},{%8,%9},{%0,%1,%2,%3};"
        : "+f"(d0), "+f"(d1), "+f"(d2), "+f"(d3)
        : "r"(a0), "r"(a1), "r"(a2), "r"(a3), "r"(b0), "r"(b1));
}

// ---------------- prep 1: column norms + folded alpha const ----------------
// exponent(p) = -c*p^2 + c*pi*p + la', la' = -10*log2e*alpha - c*pi^2/4,
// where p = asin(ip), c = 5*log2(e).
__global__ void prep1(const float* __restrict__ mus, const float* __restrict__ alphas) {
    int n = blockIdx.x * blockDim.x + threadIdx.x;
    if (n >= KPROTO) return;
    float s = 0.0f;
#pragma unroll 8
    for (int d = 0; d < DDIM; d++) {
        float v = mus[d * KPROTO + n];
        s = fmaf(v, v, s);
    }
    g_inv[n] = rsqrtf(s);
    g_la[n]  = fmaf(-14.4269504088896340f, alphas[n], -17.7985387f);
}

// ---------------- prep 2: B-hi fragments, packed per nb-pair ----------------
__global__ void prep2(const float* __restrict__ mus) {
    int gid  = blockIdx.x * blockDim.x + threadIdx.x;   // 16384 threads
    int lane = gid & 31;
    int f    = gid >> 5;            // 0..511 = nbpair*8 + ks
    int np   = f >> 3;
    int ks   = f & 7;
    int g    = lane >> 2;
    int t4   = lane & 3;
    int k0   = ks * 16 + 2 * t4;
    int nE   = (2 * np) * 8 + g;
    int nO   = nE + 8;
    float iE = g_inv[nE], iO = g_inv[nO];
    float e0 = mus[(k0 + 0) * KPROTO + nE] * iE;
    float e1 = mus[(k0 + 1) * KPROTO + nE] * iE;
    float e2 = mus[(k0 + 8) * KPROTO + nE] * iE;
    float e3 = mus[(k0 + 9) * KPROTO + nE] * iE;
    float o0 = mus[(k0 + 0) * KPROTO + nO] * iO;
    float o1 = mus[(k0 + 1) * KPROTO + nO] * iO;
    float o2 = mus[(k0 + 8) * KPROTO + nO] * iO;
    float o3 = mus[(k0 + 9) * KPROTO + nO] * iO;
    uint4 o;
    o.x = pack_h2(e0, e1);
    o.y = pack_h2(e2, e3);
    o.z = pack_h2(o0, o1);
    o.w = pack_h2(o2, o3);
    g_B[f * 32 + lane] = o;
}

// ---------------- prep 3: A fragments (fp16 hi) ----------------
__global__ void prepA(const float* __restrict__ xs) {
    int tid  = threadIdx.x;
    int ks   = tid >> 5;
    int lane = tid & 31;
    int mb   = blockIdx.x;          // 0..4095
    int g    = lane >> 2;
    int t4   = lane & 3;
    int r0 = mb * 16 + g;
    int r1 = r0 + 8;
    int c0 = ks * 16 + 2 * t4;
    float2 p00 = *(const float2*)&xs[(size_t)r0 * DDIM + c0];
    float2 p01 = *(const float2*)&xs[(size_t)r0 * DDIM + c0 + 8];
    float2 p10 = *(const float2*)&xs[(size_t)r1 * DDIM + c0];
    float2 p11 = *(const float2*)&xs[(size_t)r1 * DDIM + c0 + 8];
    uint4 oh;
    oh.x = pack_h2(p00.x, p00.y);
    oh.y = pack_h2(p10.x, p10.y);
    oh.z = pack_h2(p01.x, p01.y);
    oh.w = pack_h2(p11.x, p11.y);
    g_Ah[((size_t)mb * 8 + ks) * 32 + lane] = oh;
}

// ---------------- main: single-product mma + asin-based epilogue ----------------
// Grid = 4096 one-warp blocks. Warp w: strips 2*(w>>1), 2*(w>>1)+1;
// nb-pair range: [(w&1)*32, +32). Partials to g_S[half][row]; finalize kernel sums.
__global__ __launch_bounds__(32, 16)
void main_kernel() {
    const int lane = threadIdx.x;
    const int w    = blockIdx.x;
    const int half = w & 1;
    const int sid  = w >> 1;          // 0..2047
    const int g    = lane >> 2;
    const int t4   = lane & 3;
    const int mb0  = sid * 2;
    const int first = half * 32;

    // A fragments for both strips: register-resident
    uint4 A0[8], A1[8];
    {
        const uint4* p0 = g_Ah + (size_t)mb0 * 256 + lane;
#pragma unroll
        for (int ks = 0; ks < 8; ks++) { A0[ks] = p0[ks * 32]; A1[ks] = p0[256 + ks * 32]; }
    }

    // asin Taylor (odd, deg 9) packed coeffs
    const ull CA1 = pack2(0.16666667f,   0.16666667f);
    const ull CA2 = pack2(0.075f,        0.075f);
    const ull CA3 = pack2(0.044642857f,  0.044642857f);
    const ull CA4 = pack2(0.030381944f,  0.030381944f);

    auto tpair = [&](ull x2, float laa, float lab) -> float {
        ull u  = mul2(x2, x2);
        ull q  = fma2(CA4, u, CA3);
        q = fma2(q, u, CA2);
        q = fma2(q, u, CA1);
        ull xu = mul2(x2, u);
        ull p2 = fma2(xu, q, x2);     // asin(x)
        float p0, p1; unpack2(p2, p0, p1);
        float z0 = fmaf(p0, fmaf(p0, -7.2134752f, 22.6618023f), laa);
        float z1 = fmaf(p1, fmaf(p1, -7.2134752f, 22.6618023f), lab);
        return ex2(z0) + ex2(z1);
    };

    float s0 = 0.0f, s1 = 0.0f, s2 = 0.0f, s3 = 0.0f;
    const float2* la_p = (const float2*)g_la;
    ull ipp[8];

    auto epi0 = [&](int itp) {
        const float2* lp = la_p + itp * 8 + t4;
        float2 laE = lp[0];
        float2 laO = lp[4];
        s0 += tpair(ipp[0], laE.x, laE.y) + tpair(ipp[2], laO.x, laO.y);
        s1 += tpair(ipp[1], laE.x, laE.y) + tpair(ipp[3], laO.x, laO.y);
    };
    auto epi1 = [&](int itp) {
        const float2* lp = la_p + itp * 8 + t4;
        float2 laE = lp[0];
        float2 laO = lp[4];
        s2 += tpair(ipp[4], laE.x, laE.y) + tpair(ipp[6], laO.x, laO.y);
        s3 += tpair(ipp[5], laE.x, laE.y) + tpair(ipp[7], laO.x, laO.y);
    };

    auto body = [&](int it, bool epi) {
        const uint4* pB = g_B + it * 256 + lane;
        uint4 b0 = pB[0], b1 = pB[32], b2 = pB[64], b3 = pB[96];

        float E00=0,E01=0,E02=0,E03=0;
        float E10=0,E11=0,E12=0,E13=0;
        float O00=0,O01=0,O02=0,O03=0;
        float O10=0,O11=0,O12=0,O13=0;

        // ks 0..3
        mma16816h(E00,E01,E02,E03, A0[0].x,A0[0].y,A0[0].z,A0[0].w, b0.x,b0.y);
        mma16816h(E10,E11,E12,E13, A1[0].x,A1[0].y,A1[0].z,A1[0].w, b0.x,b0.y);
        mma16816h(O00,O01,O02,O03, A0[0].x,A0[0].y,A0[0].z,A0[0].w, b0.z,b0.w);
        mma16816h(O10,O11,O12,O13, A1[0].x,A1[0].y,A1[0].z,A1[0].w, b0.z,b0.w);
        mma16816h(E00,E01,E02,E03, A0[1].x,A0[1].y,A0[1].z,A0[1].w, b1.x,b1.y);
        mma16816h(E10,E11,E12,E13, A1[1].x,A1[1].y,A1[1].z,A1[1].w, b1.x,b1.y);
        mma16816h(O00,O01,O02,O03, A0[1].x,A0[1].y,A0[1].z,A0[1].w, b1.z,b1.w);
        mma16816h(O10,O11,O12,O13, A1[1].x,A1[1].y,A1[1].z,A1[1].w, b1.z,b1.w);
        mma16816h(E00,E01,E02,E03, A0[2].x,A0[2].y,A0[2].z,A0[2].w, b2.x,b2.y);
        mma16816h(E10,E11,E12,E13, A1[2].x,A1[2].y,A1[2].z,A1[2].w, b2.x,b2.y);
        mma16816h(O00,O01,O02,O03, A0[2].x,A0[2].y,A0[2].z,A0[2].w, b2.z,b2.w);
        mma16816h(O10,O11,O12,O13, A1[2].x,A1[2].y,A1[2].z,A1[2].w, b2.z,b2.w);
        mma16816h(E00,E01,E02,E03, A0[3].x,A0[3].y,A0[3].z,A0[3].w, b3.x,b3.y);
        mma16816h(E10,E11,E12,E13, A1[3].x,A1[3].y,A1[3].z,A1[3].w, b3.x,b3.y);
        mma16816h(O00,O01,O02,O03, A0[3].x,A0[3].y,A0[3].z,A0[3].w, b3.z,b3.w);
        mma16816h(O10,O11,O12,O13, A1[3].x,A1[3].y,A1[3].z,A1[3].w, b3.z,b3.w);

        // issue back-half loads before the epilogue so the epilogue covers them
        uint4 b4 = pB[128], b5 = pB[160], b6 = pB[192], b7 = pB[224];

        if (epi) epi0(it - 1);

        // ks 4..7
        mma16816h(E00,E01,E02,E03, A0[4].x,A0[4].y,A0[4].z,A0[4].w, b4.x,b4.y);
        mma16816h(E10,E11,E12,E13, A1[4].x,A1[4].y,A1[4].z,A1[4].w, b4.x,b4.y);
        mma16816h(O00,O01,O02,O03, A0[4].x,A0[4].y,A0[4].z,A0[4].w, b4.z,b4.w);
        mma16816h(O10,O11,O12,O13, A1[4].x,A1[4].y,A1[4].z,A1[4].w, b4.z,b4.w);
        mma16816h(E00,E01,E02,E03, A0[5].x,A0[5].y,A0[5].z,A0[5].w, b5.x,b5.y);
        mma16816h(E10,E11,E12,E13, A1[5].x,A1[5].y,A1[5].z,A1[5].w, b5.x,b5.y);
        mma16816h(O00,O01,O02,O03, A0[5].x,A0[5].y,A0[5].z,A0[5].w, b5.z,b5.w);
        mma16816h(O10,O11,O12,O13, A1[5].x,A1[5].y,A1[5].z,A1[5].w, b5.z,b5.w);
        mma16816h(E00,E01,E02,E03, A0[6].x,A0[6].y,A0[6].z,A0[6].w, b6.x,b6.y);
        mma16816h(E10,E11,E12,E13, A1[6].x,A1[6].y,A1[6].z,A1[6].w, b6.x,b6.y);
        mma16816h(O00,O01,O02,O03, A0[6].x,A0[6].y,A0[6].z,A0[6].w, b6.z,b6.w);
        mma16816h(O10,O11,O12,O13, A1[6].x,A1[6].y,A1[6].z,A1[6].w, b6.z,b6.w);
        mma16816h(E00,E01,E02,E03, A0[7].x,A0[7].y,A0[7].z,A0[7].w, b7.x,b7.y);
        mma16816h(E10,E11,E12,E13, A1[7].x,A1[7].y,A1[7].z,A1[7].w, b7.x,b7.y);
        mma16816h(O00,O01,O02,O03, A0[7].x,A0[7].y,A0[7].z,A0[7].w, b7.z,b7.w);
        mma16816h(O10,O11,O12,O13, A1[7].x,A1[7].y,A1[7].z,A1[7].w, b7.z,b7.w);

        if (epi) epi1(it - 1);

        ipp[0] = pack2(E00, E01);  ipp[1] = pack2(E02, E03);
        ipp[2] = pack2(O00, O01);  ipp[3] = pack2(O02, O03);
        ipp[4] = pack2(E10, E11);  ipp[5] = pack2(E12, E13);
        ipp[6] = pack2(O10, O11);  ipp[7] = pack2(O12, O13);
    };

    body(first, false);                 // peeled prologue (no epilogue)
#pragma unroll 1
    for (int it = first + 1; it < first + 32; it++)
        body(it, true);
    epi0(first + 31);                   // drain
    epi1(first + 31);

    // reduce across the 4 lanes sharing the same rows (t4 = 0..3)
    s0 += __shfl_xor_sync(0xffffffffu, s0, 1);
    s0 += __shfl_xor_sync(0xffffffffu, s0, 2);
    s1 += __shfl_xor_sync(0xffffffffu, s1, 1);
    s1 += __shfl_xor_sync(0xffffffffu, s1, 2);
    s2 += __shfl_xor_sync(0xffffffffu, s2, 1);
    s2 += __shfl_xor_sync(0xffffffffu, s2, 2);
    s3 += __shfl_xor_sync(0xffffffffu, s3, 1);
    s3 += __shfl_xor_sync(0xffffffffu, s3, 2);

    if (t4 == 0) {
        float* dst = g_S + half * 65536;
        int r0 = mb0 * 16 + g;
        dst[r0]      = s0;
        dst[r0 + 8]  = s1;
        dst[r0 + 16] = s2;
        dst[r0 + 24] = s3;
    }
}

// ---------------- finalize: combine halves + softmin-with-zero ----------------
__global__ void fin_kernel(float* __restrict__ out) {
    int i = blockIdx.x * 256 + threadIdx.x;
    float S = g_S[i] + g_S[65536 + i];
    out[i] = 0.1f * log1pf(1.0f / S);
}

// ---------------- launch ----------------
extern "C" void kernel_launch(void* const* d_in, const int* in_sizes, int n_in,
                              void* d_out, int out_size) {
    const float* xs     = (const float*)d_in[0];
    const float* mus    = (const float*)d_in[1];
    const float* alphas = (const float*)d_in[2];
    float* out = (float*)d_out;

    int B = in_sizes[0] / DDIM;    // 65536

    prep1<<<(KPROTO + 255) / 256, 256>>>(mus, alphas);
    prep2<<<64, 256>>>(mus);
    prepA<<<B / 16, 256>>>(xs);
    main_kernel<<<B / 16, 32>>>();          // 4096 one-warp blocks
    fin_kernel<<<B / 256, 256>>>(out);
}

// round 11
// speedup vs baseline: 1.1952x; 1.0052x over previous
#include <cuda_runtime.h>
#include <cuda_fp16.h>
#include <cstdint>

#define DDIM   128
#define KPROTO 1024
typedef unsigned int u32;
typedef unsigned long long ull;

// Static device storage (no allocation).
__device__ uint4 g_B [64 * 8 * 32];     // 256 KB: B-hi frags [nbpair][ks][lane] = {b0E,b1E,b0O,b1O}
__device__ float g_la [KPROTO];         // -10*log2e*alpha - c*pi^2/4
__device__ float g_inv[KPROTO];         // 1/||mu_col||
__device__ float g_S  [2 * 65536];      // per-half partial sums (deterministic, no atomics)

// ---------------- helpers ----------------
__device__ __forceinline__ u32 pack_h2(float a, float b) {
    __half2 t;
    t.x = __float2half_rn(a);
    t.y = __float2half_rn(b);
    return *reinterpret_cast<u32*>(&t);
}
__device__ __forceinline__ ull pack2(float lo, float hi) {
    ull r; asm("mov.b64 %0, {%1, %2};" : "=l"(r) : "f"(lo), "f"(hi)); return r;
}
__device__ __forceinline__ void unpack2(ull v, float& lo, float& hi) {
    asm("mov.b64 {%0, %1}, %2;" : "=f"(lo), "=f"(hi) : "l"(v));
}
__device__ __forceinline__ ull fma2(ull a, ull b, ull c) {
    ull d; asm("fma.rn.f32x2 %0, %1, %2, %3;" : "=l"(d) : "l"(a), "l"(b), "l"(c)); return d;
}
__device__ __forceinline__ ull mul2(ull a, ull b) {
    ull d; asm("mul.rn.f32x2 %0, %1, %2;" : "=l"(d) : "l"(a), "l"(b)); return d;
}
__device__ __forceinline__ float ex2(float x) {
    float r; asm("ex2.approx.f32 %0, %1;" : "=f"(r) : "f"(x)); return r;
}
__device__ __forceinline__ void mma16816h(float& d0, float& d1, float& d2, float& d3,
                                          u32 a0, u32 a1, u32 a2, u32 a3,
                                          u32 b0, u32 b1) {
    asm volatile(
        "mma.sync.aligned.m16n8k16.row.col.f32.f16.f16.f32 "
        "{%0,%1,%2,%3},{%4,%5,%6,%7},{%8,%9},{%0,%1,%2,%3};"
        : "+f"(d0), "+f"(d1), "+f"(d2), "+f"(d3)
        : "r"(a0), "r"(a1), "r"(a2), "r"(a3), "r"(b0), "r"(b1));
}

// ---------------- prep 1: column norms + folded alpha const ----------------
// exponent(p) = -c*p^2 + c*pi*p + la', la' = -10*log2e*alpha - c*pi^2/4,
// where p = asin(ip), c = 5*log2(e).
__global__ void prep1(const float* __restrict__ mus, const float* __restrict__ alphas) {
    int n = blockIdx.x * blockDim.x + threadIdx.x;
    if (n >= KPROTO) return;
    float s = 0.0f;
#pragma unroll 8
    for (int d = 0; d < DDIM; d++) {
        float v = mus[d * KPROTO + n];
        s = fmaf(v, v, s);
    }
    g_inv[n] = rsqrtf(s);
    g_la[n]  = fmaf(-14.4269504088896340f, alphas[n], -17.7985387f);
}

// ---------------- prep 2: B-hi fragments, packed per nb-pair ----------------
__global__ void prep2(const float* __restrict__ mus) {
    int gid  = blockIdx.x * blockDim.x + threadIdx.x;   // 16384 threads
    int lane = gid & 31;
    int f    = gid >> 5;            // 0..511 = nbpair*8 + ks
    int np   = f >> 3;
    int ks   = f & 7;
    int g    = lane >> 2;
    int t4   = lane & 3;
    int k0   = ks * 16 + 2 * t4;
    int nE   = (2 * np) * 8 + g;
    int nO   = nE + 8;
    float iE = g_inv[nE], iO = g_inv[nO];
    float e0 = mus[(k0 + 0) * KPROTO + nE] * iE;
    float e1 = mus[(k0 + 1) * KPROTO + nE] * iE;
    float e2 = mus[(k0 + 8) * KPROTO + nE] * iE;
    float e3 = mus[(k0 + 9) * KPROTO + nE] * iE;
    float o0 = mus[(k0 + 0) * KPROTO + nO] * iO;
    float o1 = mus[(k0 + 1) * KPROTO + nO] * iO;
    float o2 = mus[(k0 + 8) * KPROTO + nO] * iO;
    float o3 = mus[(k0 + 9) * KPROTO + nO] * iO;
    uint4 o;
    o.x = pack_h2(e0, e1);
    o.y = pack_h2(e2, e3);
    o.z = pack_h2(o0, o1);
    o.w = pack_h2(o2, o3);
    g_B[f * 32 + lane] = o;
}

// ---------------- main: fused A-convert + single-product mma + epilogue ----------------
// Block = 64 threads = 2 warps; both warps share ONE 16-row strip (blockIdx.x),
// warp w handles nb-pair half [w*32, +32). A converted from xs in-kernel
// (prepA eliminated). One strip/warp -> ~96 regs -> 10 blocks (20 warps)/SM.
__global__ __launch_bounds__(64, 10)
void main_kernel(const float* __restrict__ xs) {
    const int tid  = threadIdx.x;
    const int half = tid >> 5;
    const int lane = tid & 31;
    const int g    = lane >> 2;
    const int t4   = lane & 3;
    const int strip = blockIdx.x;
    const int r0 = strip * 16 + g;
    const int r1 = r0 + 8;
    const int first = half * 32;

    // A fragments: convert 16 xs rows to fp16 in registers (one-time, 32 LDG.64)
    uint4 A[8];
    {
        const float* x0 = xs + (size_t)r0 * DDIM;
        const float* x1 = xs + (size_t)r1 * DDIM;
#pragma unroll
        for (int ks = 0; ks < 8; ks++) {
            int c0 = ks * 16 + 2 * t4;
            float2 p00 = *(const float2*)(x0 + c0);
            float2 p01 = *(const float2*)(x0 + c0 + 8);
            float2 p10 = *(const float2*)(x1 + c0);
            float2 p11 = *(const float2*)(x1 + c0 + 8);
            A[ks].x = pack_h2(p00.x, p00.y);
            A[ks].y = pack_h2(p10.x, p10.y);
            A[ks].z = pack_h2(p01.x, p01.y);
            A[ks].w = pack_h2(p11.x, p11.y);
        }
    }

    // asin Taylor (odd, deg 9) + exponent-fold constants (packed)
    const ull CA1  = pack2(0.16666667f,  0.16666667f);
    const ull CA2  = pack2(0.075f,       0.075f);
    const ull CA3  = pack2(0.044642857f, 0.044642857f);
    const ull CA4  = pack2(0.030381944f, 0.030381944f);
    const ull NEGC = pack2(-7.2134752f,  -7.2134752f);
    const ull CPI  = pack2(22.6618023f,  22.6618023f);

    auto tpair = [&](ull x2, ull la2) -> float {
        ull u  = mul2(x2, x2);
        ull q  = fma2(CA4, u, CA3);
        q = fma2(q, u, CA2);
        q = fma2(q, u, CA1);
        ull xu = mul2(x2, u);
        ull p  = fma2(xu, q, x2);     // asin(x)
        ull t  = fma2(p, NEGC, CPI);
        ull z  = fma2(p, t, la2);     // -c*p^2 + c*pi*p + la'
        float z0, z1; unpack2(z, z0, z1);
        return ex2(z0) + ex2(z1);
    };

    float s0 = 0.0f, s1 = 0.0f;
    const float2* la_p = (const float2*)g_la;
    ull ipp[4];   // [E row g | E row g+8 | O row g | O row g+8]

    auto epiE = [&](int itp) {
        float2 laE = la_p[itp * 8 + t4];
        ull la2 = pack2(laE.x, laE.y);
        s0 += tpair(ipp[0], la2);
        s1 += tpair(ipp[1], la2);
    };
    auto epiO = [&](int itp) {
        float2 laO = la_p[itp * 8 + 4 + t4];
        ull la2 = pack2(laO.x, laO.y);
        s0 += tpair(ipp[2], la2);
        s1 += tpair(ipp[3], la2);
    };

    auto body = [&](int it, bool epi) {
        const uint4* pB = g_B + it * 256 + lane;
        uint4 b0 = pB[0], b1 = pB[32], b2 = pB[64], b3 = pB[96];

        float E0=0,E1=0,E2=0,E3=0;
        float O0=0,O1=0,O2=0,O3=0;

        // ks 0..3 (2 independent chains)
        mma16816h(E0,E1,E2,E3, A[0].x,A[0].y,A[0].z,A[0].w, b0.x,b0.y);
        mma16816h(O0,O1,O2,O3, A[0].x,A[0].y,A[0].z,A[0].w, b0.z,b0.w);
        mma16816h(E0,E1,E2,E3, A[1].x,A[1].y,A[1].z,A[1].w, b1.x,b1.y);
        mma16816h(O0,O1,O2,O3, A[1].x,A[1].y,A[1].z,A[1].w, b1.z,b1.w);
        mma16816h(E0,E1,E2,E3, A[2].x,A[2].y,A[2].z,A[2].w, b2.x,b2.y);
        mma16816h(O0,O1,O2,O3, A[2].x,A[2].y,A[2].z,A[2].w, b2.z,b2.w);
        mma16816h(E0,E1,E2,E3, A[3].x,A[3].y,A[3].z,A[3].w, b3.x,b3.y);
        mma16816h(O0,O1,O2,O3, A[3].x,A[3].y,A[3].z,A[3].w, b3.z,b3.w);

        // issue back-half loads before the epilogue so the epilogue covers them
        uint4 b4 = pB[128], b5 = pB[160], b6 = pB[192], b7 = pB[224];

        if (epi) epiE(it - 1);

        // ks 4..7
        mma16816h(E0,E1,E2,E3, A[4].x,A[4].y,A[4].z,A[4].w, b4.x,b4.y);
        mma16816h(O0,O1,O2,O3, A[4].x,A[4].y,A[4].z,A[4].w, b4.z,b4.w);
        mma16816h(E0,E1,E2,E3, A[5].x,A[5].y,A[5].z,A[5].w, b5.x,b5.y);
        mma16816h(O0,O1,O2,O3, A[5].x,A[5].y,A[5].z,A[5].w, b5.z,b5.w);
        mma16816h(E0,E1,E2,E3, A[6].x,A[6].y,A[6].z,A[6].w, b6.x,b6.y);
        mma16816h(O0,O1,O2,O3, A[6].x,A[6].y,A[6].z,A[6].w, b6.z,b6.w);
        mma16816h(E0,E1,E2,E3, A[7].x,A[7].y,A[7].z,A[7].w, b7.x,b7.y);
        mma16816h(O0,O1,O2,O3, A[7].x,A[7].y,A[7].z,A[7].w, b7.z,b7.w);

        if (epi) epiO(it - 1);

        ipp[0] = pack2(E0, E1);   // row g (cols 2t4, 2t4+1)
        ipp[1] = pack2(E2, E3);   // row g+8
        ipp[2] = pack2(O0, O1);
        ipp[3] = pack2(O2, O3);
    };

    body(first, false);                  // peeled prologue
#pragma unroll 1
    for (int it = first + 1; it < first + 32; it++)
        body(it, true);
    epiE(first + 31);                    // drain
    epiO(first + 31);

    // reduce across the 4 lanes sharing the same rows (t4 = 0..3)
    s0 += __shfl_xor_sync(0xffffffffu, s0, 1);
    s0 += __shfl_xor_sync(0xffffffffu, s0, 2);
    s1 += __shfl_xor_sync(0xffffffffu, s1, 1);
    s1 += __shfl_xor_sync(0xffffffffu, s1, 2);

    if (t4 == 0) {
        float* dst = g_S + half * 65536;
        dst[r0] = s0;
        dst[r1] = s1;
    }
}

// ---------------- finalize: combine halves + softmin-with-zero ----------------
__global__ void fin_kernel(float* __restrict__ out) {
    int i = blockIdx.x * 256 + threadIdx.x;
    float S = g_S[i] + g_S[65536 + i];
    out[i] = 0.1f * log1pf(1.0f / S);
}

// ---------------- launch ----------------
extern "C" void kernel_launch(void* const* d_in, const int* in_sizes, int n_in,
                              void* d_out, int out_size) {
    const float* xs     = (const float*)d_in[0];
    const float* mus    = (const float*)d_in[1];
    const float* alphas = (const float*)d_in[2];
    float* out = (float*)d_out;

    int B = in_sizes[0] / DDIM;    // 65536

    prep1<<<(KPROTO + 255) / 256, 256>>>(mus, alphas);
    prep2<<<64, 256>>>(mus);
    main_kernel<<<B / 16, 64>>>(xs);        // 4096 blocks x 2 warps
    fin_kernel<<<B / 256, 256>>>(out);
}

// round 12
// speedup vs baseline: 1.2227x; 1.0230x over previous
#include <cuda_runtime.h>
#include <cuda_fp16.h>
#include <cstdint>

#define DDIM   128
#define KPROTO 1024
typedef unsigned int u32;
typedef unsigned long long ull;

// Static device storage (no allocation).
__device__ uint4 g_B [64 * 8 * 32];     // 256 KB: B-hi frags [nbpair][ks][lane] = {b0E,b1E,b0O,b1O}
__device__ float g_la [KPROTO];         // -10*log2e*alpha - c*pi^2/4
__device__ float g_inv[KPROTO];         // 1/||mu_col||

// ---------------- helpers ----------------
__device__ __forceinline__ u32 pack_h2(float a, float b) {
    __half2 t;
    t.x = __float2half_rn(a);
    t.y = __float2half_rn(b);
    return *reinterpret_cast<u32*>(&t);
}
__device__ __forceinline__ ull pack2(float lo, float hi) {
    ull r; asm("mov.b64 %0, {%1, %2};" : "=l"(r) : "f"(lo), "f"(hi)); return r;
}
__device__ __forceinline__ void unpack2(ull v, float& lo, float& hi) {
    asm("mov.b64 {%0, %1}, %2;" : "=f"(lo), "=f"(hi) : "l"(v));
}
__device__ __forceinline__ ull fma2(ull a, ull b, ull c) {
    ull d; asm("fma.rn.f32x2 %0, %1, %2, %3;" : "=l"(d) : "l"(a), "l"(b), "l"(c)); return d;
}
__device__ __forceinline__ ull mul2(ull a, ull b) {
    ull d; asm("mul.rn.f32x2 %0, %1, %2;" : "=l"(d) : "l"(a), "l"(b)); return d;
}
__device__ __forceinline__ float ex2(float x) {
    float r; asm("ex2.approx.f32 %0, %1;" : "=f"(r) : "f"(x)); return r;
}
__device__ __forceinline__ void mma16816h(float& d0, float& d1, float& d2, float& d3,
                                          u32 a0, u32 a1, u32 a2, u32 a3,
                                          u32 b0, u32 b1) {
    asm volatile(
        "mma.sync.aligned.m16n8k16.row.col.f32.f16.f16.f32 "
        "{%0,%1,%2,%3},{%4,%5,%6,%7},{%8,%9},{%0,%1,%2,%3};"
        : "+f"(d0), "+f"(d1), "+f"(d2), "+f"(d3)
        : "r"(a0), "r"(a1), "r"(a2), "r"(a3), "r"(b0), "r"(b1));
}

// ---------------- prep 1: column norms + folded alpha const ----------------
__global__ void prep1(const float* __restrict__ mus, const float* __restrict__ alphas) {
    int n = blockIdx.x * blockDim.x + threadIdx.x;
    if (n >= KPROTO) return;
    float s = 0.0f;
#pragma unroll 8
    for (int d = 0; d < DDIM; d++) {
        float v = mus[d * KPROTO + n];
        s = fmaf(v, v, s);
    }
    g_inv[n] = rsqrtf(s);
    g_la[n]  = fmaf(-14.4269504088896340f, alphas[n], -17.7985387f);
}

// ---------------- prep 2: B-hi fragments, packed per nb-pair ----------------
__global__ void prep2(const float* __restrict__ mus) {
    int gid  = blockIdx.x * blockDim.x + threadIdx.x;   // 16384 threads
    int lane = gid & 31;
    int f    = gid >> 5;            // 0..511 = nbpair*8 + ks
    int np   = f >> 3;
    int ks   = f & 7;
    int g    = lane >> 2;
    int t4   = lane & 3;
    int k0   = ks * 16 + 2 * t4;
    int nE   = (2 * np) * 8 + g;
    int nO   = nE + 8;
    float iE = g_inv[nE], iO = g_inv[nO];
    float e0 = mus[(k0 + 0) * KPROTO + nE] * iE;
    float e1 = mus[(k0 + 1) * KPROTO + nE] * iE;
    float e2 = mus[(k0 + 8) * KPROTO + nE] * iE;
    float e3 = mus[(k0 + 9) * KPROTO + nE] * iE;
    float o0 = mus[(k0 + 0) * KPROTO + nO] * iO;
    float o1 = mus[(k0 + 1) * KPROTO + nO] * iO;
    float o2 = mus[(k0 + 8) * KPROTO + nO] * iO;
    float o3 = mus[(k0 + 9) * KPROTO + nO] * iO;
    uint4 o;
    o.x = pack_h2(e0, e1);
    o.y = pack_h2(e2, e3);
    o.z = pack_h2(o0, o1);
    o.w = pack_h2(o2, o3);
    g_B[f * 32 + lane] = o;
}

// ---------------- main: fused A-convert + mma + epilogue + in-block reduce ----------------
// Block = 64 threads = 2 warps sharing ONE 16-row strip; warp half does
// nb-pairs [half*32, +32). Per iteration: 4 independent 4-deep HMMA chains
// (Ea/Eb/Oa/Ob) — halved critical path vs R11. Final reduce in smem, direct out.
__global__ __launch_bounds__(64, 9)
void main_kernel(const float* __restrict__ xs, float* __restrict__ out) {
    __shared__ float red[2][16];

    const int tid  = threadIdx.x;
    const int half = tid >> 5;
    const int lane = tid & 31;
    const int g    = lane >> 2;
    const int t4   = lane & 3;
    const int strip = blockIdx.x;
    const int r0 = strip * 16 + g;
    const int r1 = r0 + 8;
    const int first = half * 32;

    // A fragments: convert 16 xs rows to fp16 in registers (one-time)
    uint4 A[8];
    {
        const float* x0 = xs + (size_t)r0 * DDIM;
        const float* x1 = xs + (size_t)r1 * DDIM;
#pragma unroll
        for (int ks = 0; ks < 8; ks++) {
            int c0 = ks * 16 + 2 * t4;
            float2 p00 = *(const float2*)(x0 + c0);
            float2 p01 = *(const float2*)(x0 + c0 + 8);
            float2 p10 = *(const float2*)(x1 + c0);
            float2 p11 = *(const float2*)(x1 + c0 + 8);
            A[ks].x = pack_h2(p00.x, p00.y);
            A[ks].y = pack_h2(p10.x, p10.y);
            A[ks].z = pack_h2(p01.x, p01.y);
            A[ks].w = pack_h2(p11.x, p11.y);
        }
    }

    // asin Taylor (odd, deg 9) + exponent-fold constants (packed)
    const ull CA1  = pack2(0.16666667f,  0.16666667f);
    const ull CA2  = pack2(0.075f,       0.075f);
    const ull CA3  = pack2(0.044642857f, 0.044642857f);
    const ull CA4  = pack2(0.030381944f, 0.030381944f);
    const ull NEGC = pack2(-7.2134752f,  -7.2134752f);
    const ull CPI  = pack2(22.6618023f,  22.6618023f);

    auto tpair = [&](ull x2, ull la2) -> float {
        ull u  = mul2(x2, x2);
        ull q  = fma2(CA4, u, CA3);
        q = fma2(q, u, CA2);
        q = fma2(q, u, CA1);
        ull xu = mul2(x2, u);
        ull p  = fma2(xu, q, x2);     // asin(x)
        ull t  = fma2(p, NEGC, CPI);
        ull z  = fma2(p, t, la2);     // -c*p^2 + c*pi*p + la'
        float z0, z1; unpack2(z, z0, z1);
        return ex2(z0) + ex2(z1);
    };

    float s0 = 0.0f, s1 = 0.0f;
    const float2* la_p = (const float2*)g_la;
    ull ipp[4];   // [E row g | E row g+8 | O row g | O row g+8]

    auto epiE = [&](int itp) {
        float2 laE = la_p[itp * 8 + t4];
        ull la2 = pack2(laE.x, laE.y);
        s0 += tpair(ipp[0], la2);
        s1 += tpair(ipp[1], la2);
    };
    auto epiO = [&](int itp) {
        float2 laO = la_p[itp * 8 + 4 + t4];
        ull la2 = pack2(laO.x, laO.y);
        s0 += tpair(ipp[2], la2);
        s1 += tpair(ipp[3], la2);
    };

    auto body = [&](int it, bool epi) {
        const uint4* pB = g_B + it * 256 + lane;
        // all 8 loads upfront: MLP=8
        uint4 b0 = pB[0],   b1 = pB[32],  b2 = pB[64],  b3 = pB[96];
        uint4 b4 = pB[128], b5 = pB[160], b6 = pB[192], b7 = pB[224];

        float Ea0=0,Ea1=0,Ea2=0,Ea3=0;   // E cols, ks0-3
        float Eb0=0,Eb1=0,Eb2=0,Eb3=0;   // E cols, ks4-7
        float Oa0=0,Oa1=0,Oa2=0,Oa3=0;   // O cols, ks0-3
        float Ob0=0,Ob1=0,Ob2=0,Ob3=0;   // O cols, ks4-7

        // 4 independent chains, round-robin issue
        mma16816h(Ea0,Ea1,Ea2,Ea3, A[0].x,A[0].y,A[0].z,A[0].w, b0.x,b0.y);
        mma16816h(Oa0,Oa1,Oa2,Oa3, A[0].x,A[0].y,A[0].z,A[0].w, b0.z,b0.w);
        mma16816h(Eb0,Eb1,Eb2,Eb3, A[4].x,A[4].y,A[4].z,A[4].w, b4.x,b4.y);
        mma16816h(Ob0,Ob1,Ob2,Ob3, A[4].x,A[4].y,A[4].z,A[4].w, b4.z,b4.w);
        mma16816h(Ea0,Ea1,Ea2,Ea3, A[1].x,A[1].y,A[1].z,A[1].w, b1.x,b1.y);
        mma16816h(Oa0,Oa1,Oa2,Oa3, A[1].x,A[1].y,A[1].z,A[1].w, b1.z,b1.w);
        mma16816h(Eb0,Eb1,Eb2,Eb3, A[5].x,A[5].y,A[5].z,A[5].w, b5.x,b5.y);
        mma16816h(Ob0,Ob1,Ob2,Ob3, A[5].x,A[5].y,A[5].z,A[5].w, b5.z,b5.w);

        if (epi) epiE(it - 1);

        mma16816h(Ea0,Ea1,Ea2,Ea3, A[2].x,A[2].y,A[2].z,A[2].w, b2.x,b2.y);
        mma16816h(Oa0,Oa1,Oa2,Oa3, A[2].x,A[2].y,A[2].z,A[2].w, b2.z,b2.w);
        mma16816h(Eb0,Eb1,Eb2,Eb3, A[6].x,A[6].y,A[6].z,A[6].w, b6.x,b6.y);
        mma16816h(Ob0,Ob1,Ob2,Ob3, A[6].x,A[6].y,A[6].z,A[6].w, b6.z,b6.w);
        mma16816h(Ea0,Ea1,Ea2,Ea3, A[3].x,A[3].y,A[3].z,A[3].w, b3.x,b3.y);
        mma16816h(Oa0,Oa1,Oa2,Oa3, A[3].x,A[3].y,A[3].z,A[3].w, b3.z,b3.w);
        mma16816h(Eb0,Eb1,Eb2,Eb3, A[7].x,A[7].y,A[7].z,A[7].w, b7.x,b7.y);
        mma16816h(Ob0,Ob1,Ob2,Ob3, A[7].x,A[7].y,A[7].z,A[7].w, b7.z,b7.w);

        if (epi) epiO(it - 1);

        ipp[0] = pack2(Ea0 + Eb0, Ea1 + Eb1);   // row g (E cols)
        ipp[1] = pack2(Ea2 + Eb2, Ea3 + Eb3);   // row g+8
        ipp[2] = pack2(Oa0 + Ob0, Oa1 + Ob1);
        ipp[3] = pack2(Oa2 + Ob2, Oa3 + Ob3);
    };

    body(first, false);                  // peeled prologue
#pragma unroll 1
    for (int it = first + 1; it < first + 32; it++)
        body(it, true);
    epiE(first + 31);                    // drain
    epiO(first + 31);

    // reduce across the 4 lanes sharing the same rows (t4 = 0..3)
    s0 += __shfl_xor_sync(0xffffffffu, s0, 1);
    s0 += __shfl_xor_sync(0xffffffffu, s0, 2);
    s1 += __shfl_xor_sync(0xffffffffu, s1, 1);
    s1 += __shfl_xor_sync(0xffffffffu, s1, 2);

    if (t4 == 0) {
        red[half][g]     = s0;
        red[half][g + 8] = s1;
    }
    __syncthreads();
    if (tid < 16) {
        float S = red[0][tid] + red[1][tid];
        out[strip * 16 + tid] = 0.1f * log1pf(1.0f / S);
    }
}

// ---------------- launch ----------------
extern "C" void kernel_launch(void* const* d_in, const int* in_sizes, int n_in,
                              void* d_out, int out_size) {
    const float* xs     = (const float*)d_in[0];
    const float* mus    = (const float*)d_in[1];
    const float* alphas = (const float*)d_in[2];
    float* out = (float*)d_out;

    int B = in_sizes[0] / DDIM;    // 65536

    prep1<<<(KPROTO + 255) / 256, 256>>>(mus, alphas);
    prep2<<<64, 256>>>(mus);
    main_kernel<<<B / 16, 64>>>(xs, out);   // 4096 blocks x 2 warps
}

// round 13
// speedup vs baseline: 1.2629x; 1.0329x over previous
#include <cuda_runtime.h>
#include <cuda_fp16.h>
#include <cstdint>

#define DDIM   128
#define KPROTO 1024
typedef unsigned int u32;
typedef unsigned long long ull;

// Static device storage (no allocation).
__device__ uint4 g_B [64 * 8 * 32];     // 256 KB: B-hi frags [nbpair][ks][lane] = {b0E,b1E,b0O,b1O}
__device__ float g_la [KPROTO];         // -10*log2e*alpha - c*pi^2/4
__device__ float g_inv[KPROTO];         // 1/||mu_col||

// ---------------- helpers ----------------
__device__ __forceinline__ u32 pack_h2(float a, float b) {
    __half2 t;
    t.x = __float2half_rn(a);
    t.y = __float2half_rn(b);
    return *reinterpret_cast<u32*>(&t);
}
__device__ __forceinline__ ull pack2(float lo, float hi) {
    ull r; asm("mov.b64 %0, {%1, %2};" : "=l"(r) : "f"(lo), "f"(hi)); return r;
}
__device__ __forceinline__ void unpack2(ull v, float& lo, float& hi) {
    asm("mov.b64 {%0, %1}, %2;" : "=f"(lo), "=f"(hi) : "l"(v));
}
__device__ __forceinline__ ull fma2(ull a, ull b, ull c) {
    ull d; asm("fma.rn.f32x2 %0, %1, %2, %3;" : "=l"(d) : "l"(a), "l"(b), "l"(c)); return d;
}
__device__ __forceinline__ ull mul2(ull a, ull b) {
    ull d; asm("mul.rn.f32x2 %0, %1, %2;" : "=l"(d) : "l"(a), "l"(b)); return d;
}
__device__ __forceinline__ float ex2(float x) {
    float r; asm("ex2.approx.f32 %0, %1;" : "=f"(r) : "f"(x)); return r;
}
__device__ __forceinline__ void mma16816h(float& d0, float& d1, float& d2, float& d3,
                                          u32 a0, u32 a1, u32 a2, u32 a3,
                                          u32 b0, u32 b1) {
    asm volatile(
        "mma.sync.aligned.m16n8k16.row.col.f32.f16.f16.f32 "
        "{%0,%1,%2,%3},{%4,%5,%6,%7},{%8,%9},{%0,%1,%2,%3};"
        : "+f"(d0), "+f"(d1), "+f"(d2), "+f"(d3)
        : "r"(a0), "r"(a1), "r"(a2), "r"(a3), "r"(b0), "r"(b1));
}

// ---------------- prep 1: warp-per-column norms + folded alpha const ----------------
// 1024 warps; lane l of warp n loads mus[l + 32i][n] (i=0..3), shuffle-reduce.
__global__ void prepNorm(const float* __restrict__ mus, const float* __restrict__ alphas) {
    int gtid = blockIdx.x * blockDim.x + threadIdx.x;
    int n    = gtid >> 5;          // column = warp id
    int lane = gtid & 31;
    float s = 0.0f;
#pragma unroll
    for (int i = 0; i < 4; i++) {
        float v = mus[(lane + 32 * i) * KPROTO + n];
        s = fmaf(v, v, s);
    }
#pragma unroll
    for (int off = 16; off > 0; off >>= 1)
        s += __shfl_xor_sync(0xffffffffu, s, off);
    if (lane == 0) {
        g_inv[n] = rsqrtf(s);
        g_la[n]  = fmaf(-14.4269504088896340f, alphas[n], -17.7985387f);
    }
}

// ---------------- prep 2: B-hi fragments, packed per nb-pair ----------------
__global__ void prep2(const float* __restrict__ mus) {
    int gid  = blockIdx.x * blockDim.x + threadIdx.x;   // 16384 threads
    int lane = gid & 31;
    int f    = gid >> 5;            // 0..511 = nbpair*8 + ks
    int np   = f >> 3;
    int ks   = f & 7;
    int g    = lane >> 2;
    int t4   = lane & 3;
    int k0   = ks * 16 + 2 * t4;
    int nE   = (2 * np) * 8 + g;
    int nO   = nE + 8;
    float iE = g_inv[nE], iO = g_inv[nO];
    float e0 = mus[(k0 + 0) * KPROTO + nE] * iE;
    float e1 = mus[(k0 + 1) * KPROTO + nE] * iE;
    float e2 = mus[(k0 + 8) * KPROTO + nE] * iE;
    float e3 = mus[(k0 + 9) * KPROTO + nE] * iE;
    float o0 = mus[(k0 + 0) * KPROTO + nO] * iO;
    float o1 = mus[(k0 + 1) * KPROTO + nO] * iO;
    float o2 = mus[(k0 + 8) * KPROTO + nO] * iO;
    float o3 = mus[(k0 + 9) * KPROTO + nO] * iO;
    uint4 o;
    o.x = pack_h2(e0, e1);
    o.y = pack_h2(e2, e3);
    o.z = pack_h2(o0, o1);
    o.w = pack_h2(o2, o3);
    g_B[f * 32 + lane] = o;
}

// ---------------- main: fused A-convert + mma + epilogue + in-block reduce ----------------
// Block = 64 threads = 2 warps sharing ONE 16-row strip; warp half does
// nb-pairs [half*32, +32). Per iteration: 4 independent 4-deep HMMA chains.
__global__ __launch_bounds__(64, 9)
void main_kernel(const float* __restrict__ xs, float* __restrict__ out) {
    __shared__ float red[2][16];

    const int tid  = threadIdx.x;
    const int half = tid >> 5;
    const int lane = tid & 31;
    const int g    = lane >> 2;
    const int t4   = lane & 3;
    const int strip = blockIdx.x;
    const int r0 = strip * 16 + g;
    const int r1 = r0 + 8;
    const int first = half * 32;

    // A fragments: convert 16 xs rows to fp16 in registers (one-time)
    uint4 A[8];
    {
        const float* x0 = xs + (size_t)r0 * DDIM;
        const float* x1 = xs + (size_t)r1 * DDIM;
#pragma unroll
        for (int ks = 0; ks < 8; ks++) {
            int c0 = ks * 16 + 2 * t4;
            float2 p00 = *(const float2*)(x0 + c0);
            float2 p01 = *(const float2*)(x0 + c0 + 8);
            float2 p10 = *(const float2*)(x1 + c0);
            float2 p11 = *(const float2*)(x1 + c0 + 8);
            A[ks].x = pack_h2(p00.x, p00.y);
            A[ks].y = pack_h2(p10.x, p10.y);
            A[ks].z = pack_h2(p01.x, p01.y);
            A[ks].w = pack_h2(p11.x, p11.y);
        }
    }

    // asin Taylor (odd, deg 9) + exponent-fold constants (packed)
    const ull CA1  = pack2(0.16666667f,  0.16666667f);
    const ull CA2  = pack2(0.075f,       0.075f);
    const ull CA3  = pack2(0.044642857f, 0.044642857f);
    const ull CA4  = pack2(0.030381944f, 0.030381944f);
    const ull NEGC = pack2(-7.2134752f,  -7.2134752f);
    const ull CPI  = pack2(22.6618023f,  22.6618023f);

    auto tpair = [&](ull x2, ull la2) -> float {
        ull u  = mul2(x2, x2);
        ull q  = fma2(CA4, u, CA3);
        q = fma2(q, u, CA2);
        q = fma2(q, u, CA1);
        ull xu = mul2(x2, u);
        ull p  = fma2(xu, q, x2);     // asin(x)
        ull t  = fma2(p, NEGC, CPI);
        ull z  = fma2(p, t, la2);     // -c*p^2 + c*pi*p + la'
        float z0, z1; unpack2(z, z0, z1);
        return ex2(z0) + ex2(z1);
    };

    float s0 = 0.0f, s1 = 0.0f;
    const float2* la_p = (const float2*)g_la;
    ull ipp[4];   // [E row g | E row g+8 | O row g | O row g+8]

    auto epiE = [&](int itp) {
        float2 laE = la_p[itp * 8 + t4];
        ull la2 = pack2(laE.x, laE.y);
        s0 += tpair(ipp[0], la2);
        s1 += tpair(ipp[1], la2);
    };
    auto epiO = [&](int itp) {
        float2 laO = la_p[itp * 8 + 4 + t4];
        ull la2 = pack2(laO.x, laO.y);
        s0 += tpair(ipp[2], la2);
        s1 += tpair(ipp[3], la2);
    };

    auto body = [&](int it, bool epi) {
        const uint4* pB = g_B + it * 256 + lane;
        // all 8 loads upfront: MLP=8
        uint4 b0 = pB[0],   b1 = pB[32],  b2 = pB[64],  b3 = pB[96];
        uint4 b4 = pB[128], b5 = pB[160], b6 = pB[192], b7 = pB[224];

        float Ea0=0,Ea1=0,Ea2=0,Ea3=0;   // E cols, ks0-3
        float Eb0=0,Eb1=0,Eb2=0,Eb3=0;   // E cols, ks4-7
        float Oa0=0,Oa1=0,Oa2=0,Oa3=0;   // O cols, ks0-3
        float Ob0=0,Ob1=0,Ob2=0,Ob3=0;   // O cols, ks4-7

        // 4 independent chains, round-robin issue
        mma16816h(Ea0,Ea1,Ea2,Ea3, A[0].x,A[0].y,A[0].z,A[0].w, b0.x,b0.y);
        mma16816h(Oa0,Oa1,Oa2,Oa3, A[0].x,A[0].y,A[0].z,A[0].w, b0.z,b0.w);
        mma16816h(Eb0,Eb1,Eb2,Eb3, A[4].x,A[4].y,A[4].z,A[4].w, b4.x,b4.y);
        mma16816h(Ob0,Ob1,Ob2,Ob3, A[4].x,A[4].y,A[4].z,A[4].w, b4.z,b4.w);
        mma16816h(Ea0,Ea1,Ea2,Ea3, A[1].x,A[1].y,A[1].z,A[1].w, b1.x,b1.y);
        mma16816h(Oa0,Oa1,Oa2,Oa3, A[1].x,A[1].y,A[1].z,A[1].w, b1.z,b1.w);
        mma16816h(Eb0,Eb1,Eb2,Eb3, A[5].x,A[5].y,A[5].z,A[5].w, b5.x,b5.y);
        mma16816h(Ob0,Ob1,Ob2,Ob3, A[5].x,A[5].y,A[5].z,A[5].w, b5.z,b5.w);

        if (epi) epiE(it - 1);

        mma16816h(Ea0,Ea1,Ea2,Ea3, A[2].x,A[2].y,A[2].z,A[2].w, b2.x,b2.y);
        mma16816h(Oa0,Oa1,Oa2,Oa3, A[2].x,A[2].y,A[2].z,A[2].w, b2.z,b2.w);
        mma16816h(Eb0,Eb1,Eb2,Eb3, A[6].x,A[6].y,A[6].z,A[6].w, b6.x,b6.y);
        mma16816h(Ob0,Ob1,Ob2,Ob3, A[6].x,A[6].y,A[6].z,A[6].w, b6.z,b6.w);
        mma16816h(Ea0,Ea1,Ea2,Ea3, A[3].x,A[3].y,A[3].z,A[3].w, b3.x,b3.y);
        mma16816h(Oa0,Oa1,Oa2,Oa3, A[3].x,A[3].y,A[3].z,A[3].w, b3.z,b3.w);
        mma16816h(Eb0,Eb1,Eb2,Eb3, A[7].x,A[7].y,A[7].z,A[7].w, b7.x,b7.y);
        mma16816h(Ob0,Ob1,Ob2,Ob3, A[7].x,A[7].y,A[7].z,A[7].w, b7.z,b7.w);

        if (epi) epiO(it - 1);

        ipp[0] = pack2(Ea0 + Eb0, Ea1 + Eb1);   // row g (E cols)
        ipp[1] = pack2(Ea2 + Eb2, Ea3 + Eb3);   // row g+8
        ipp[2] = pack2(Oa0 + Ob0, Oa1 + Ob1);
        ipp[3] = pack2(Oa2 + Ob2, Oa3 + Ob3);
    };

    body(first, false);                  // peeled prologue
#pragma unroll 1
    for (int it = first + 1; it < first + 32; it++)
        body(it, true);
    epiE(first + 31);                    // drain
    epiO(first + 31);

    // reduce across the 4 lanes sharing the same rows (t4 = 0..3)
    s0 += __shfl_xor_sync(0xffffffffu, s0, 1);
    s0 += __shfl_xor_sync(0xffffffffu, s0, 2);
    s1 += __shfl_xor_sync(0xffffffffu, s1, 1);
    s1 += __shfl_xor_sync(0xffffffffu, s1, 2);

    if (t4 == 0) {
        red[half][g]     = s0;
        red[half][g + 8] = s1;
    }
    __syncthreads();
    if (tid < 16) {
        float S = red[0][tid] + red[1][tid];
        out[strip * 16 + tid] = 0.1f * log1pf(1.0f / S);
    }
}

// ---------------- launch ----------------
extern "C" void kernel_launch(void* const* d_in, const int* in_sizes, int n_in,
                              void* d_out, int out_size) {
    const float* xs     = (const float*)d_in[0];
    const float* mus    = (const float*)d_in[1];
    const float* alphas = (const float*)d_in[2];
    float* out = (float*)d_out;

    int B = in_sizes[0] / DDIM;    // 65536

    prepNorm<<<KPROTO * 32 / 256, 256>>>(mus, alphas);   // 128 blocks, warp per column
    prep2<<<64, 256>>>(mus);
    main_kernel<<<B / 16, 64>>>(xs, out);                // 4096 blocks x 2 warps
}

// round 14
// speedup vs baseline: 1.2960x; 1.0262x over previous
#include <cuda_runtime.h>
#include <cuda_fp16.h>
#include <cstdint>

#define DDIM   128
#define KPROTO 1024
typedef unsigned int u32;
typedef unsigned long long ull;

// Static device storage (no allocation).
__device__ uint4 g_B [64 * 8 * 32];     // 256 KB: B-hi frags [nbpair][ks][lane] = {b0E,b1E,b0O,b1O}
__device__ float g_la [KPROTO];         // -10*log2e*alpha - c*pi^2/4

// ---------------- helpers ----------------
__device__ __forceinline__ u32 pack_h2(float a, float b) {
    __half2 t;
    t.x = __float2half_rn(a);
    t.y = __float2half_rn(b);
    return *reinterpret_cast<u32*>(&t);
}
__device__ __forceinline__ ull pack2(float lo, float hi) {
    ull r; asm("mov.b64 %0, {%1, %2};" : "=l"(r) : "f"(lo), "f"(hi)); return r;
}
__device__ __forceinline__ void unpack2(ull v, float& lo, float& hi) {
    asm("mov.b64 {%0, %1}, %2;" : "=f"(lo), "=f"(hi) : "l"(v));
}
__device__ __forceinline__ ull fma2(ull a, ull b, ull c) {
    ull d; asm("fma.rn.f32x2 %0, %1, %2, %3;" : "=l"(d) : "l"(a), "l"(b), "l"(c)); return d;
}
__device__ __forceinline__ ull mul2(ull a, ull b) {
    ull d; asm("mul.rn.f32x2 %0, %1, %2;" : "=l"(d) : "l"(a), "l"(b)); return d;
}
__device__ __forceinline__ float ex2(float x) {
    float r; asm("ex2.approx.f32 %0, %1;" : "=f"(r) : "f"(x)); return r;
}
__device__ __forceinline__ void mma16816h(float& d0, float& d1, float& d2, float& d3,
                                          u32 a0, u32 a1, u32 a2, u32 a3,
                                          u32 b0, u32 b1) {
    asm volatile(
        "mma.sync.aligned.m16n8k16.row.col.f32.f16.f16.f32 "
        "{%0,%1,%2,%3},{%4,%5,%6,%7},{%8,%9},{%0,%1,%2,%3};"
        : "+f"(d0), "+f"(d1), "+f"(d2), "+f"(d3)
        : "r"(a0), "r"(a1), "r"(a2), "r"(a3), "r"(b0), "r"(b1));
}

// ---------------- fused prep: per-block column norms + B fragment packing ----------------
// 64 blocks x 256 threads; block np owns columns [np*16, np*16+16) = its nb-pair.
// Phase 1: norms (semi-coalesced: consecutive threads -> consecutive columns).
// Phase 2: prep2's fragment packing reading inv from smem.
__global__ void prepFused(const float* __restrict__ mus, const float* __restrict__ alphas) {
    __shared__ float s_part[256];
    __shared__ float s_inv[16];

    const int tid = threadIdx.x;
    const int np  = blockIdx.x;
    const int n0  = np * 16;

    // phase 1: c = tid&15 (column), p = tid>>4 (row-chunk of 8)
    {
        int c = tid & 15, p = tid >> 4;
        float s = 0.0f;
#pragma unroll
        for (int i = 0; i < 8; i++) {
            float v = mus[(p * 8 + i) * KPROTO + n0 + c];
            s = fmaf(v, v, s);
        }
        s_part[tid] = s;
    }
    __syncthreads();
    if (tid < 16) {
        float t = 0.0f;
#pragma unroll
        for (int j = 0; j < 16; j++) t += s_part[j * 16 + tid];
        s_inv[tid] = rsqrtf(t);
        g_la[n0 + tid] = fmaf(-14.4269504088896340f, alphas[n0 + tid], -17.7985387f);
    }
    __syncthreads();

    // phase 2: fragment packing (ks = tid>>5, 8 warps = 8 ksteps)
    {
        int lane = tid & 31;
        int ks   = tid >> 5;
        int g    = lane >> 2;
        int t4   = lane & 3;
        int k0   = ks * 16 + 2 * t4;
        int nE   = n0 + g;
        int nO   = nE + 8;
        float iE = s_inv[g], iO = s_inv[g + 8];
        float e0 = mus[(k0 + 0) * KPROTO + nE] * iE;
        float e1 = mus[(k0 + 1) * KPROTO + nE] * iE;
        float e2 = mus[(k0 + 8) * KPROTO + nE] * iE;
        float e3 = mus[(k0 + 9) * KPROTO + nE] * iE;
        float o0 = mus[(k0 + 0) * KPROTO + nO] * iO;
        float o1 = mus[(k0 + 1) * KPROTO + nO] * iO;
        float o2 = mus[(k0 + 8) * KPROTO + nO] * iO;
        float o3 = mus[(k0 + 9) * KPROTO + nO] * iO;
        uint4 o;
        o.x = pack_h2(e0, e1);
        o.y = pack_h2(e2, e3);
        o.z = pack_h2(o0, o1);
        o.w = pack_h2(o2, o3);
        g_B[(np * 8 + ks) * 32 + lane] = o;
    }
}

// ---------------- main: fused A-convert + mma + epilogue + in-block reduce ----------------
// Block = 64 threads = 2 warps sharing ONE 16-row strip; warp half does
// nb-pairs [half*32, +32). 4 independent 4-deep HMMA chains; B loads in two
// batches of 4 to cap live registers (target 10 blocks/SM).
__global__ __launch_bounds__(64, 10)
void main_kernel(const float* __restrict__ xs, float* __restrict__ out) {
    __shared__ float red[2][16];

    const int tid  = threadIdx.x;
    const int half = tid >> 5;
    const int lane = tid & 31;
    const int g    = lane >> 2;
    const int t4   = lane & 3;
    const int strip = blockIdx.x;
    const int r0 = strip * 16 + g;
    const int r1 = r0 + 8;
    const int first = half * 32;

    // A fragments: convert 16 xs rows to fp16 in registers (one-time)
    uint4 A[8];
    {
        const float* x0 = xs + (size_t)r0 * DDIM;
        const float* x1 = xs + (size_t)r1 * DDIM;
#pragma unroll
        for (int ks = 0; ks < 8; ks++) {
            int c0 = ks * 16 + 2 * t4;
            float2 p00 = *(const float2*)(x0 + c0);
            float2 p01 = *(const float2*)(x0 + c0 + 8);
            float2 p10 = *(const float2*)(x1 + c0);
            float2 p11 = *(const float2*)(x1 + c0 + 8);
            A[ks].x = pack_h2(p00.x, p00.y);
            A[ks].y = pack_h2(p10.x, p10.y);
            A[ks].z = pack_h2(p01.x, p01.y);
            A[ks].w = pack_h2(p11.x, p11.y);
        }
    }

    // asin Taylor (odd, deg 9) + exponent-fold constants (packed)
    const ull CA1  = pack2(0.16666667f,  0.16666667f);
    const ull CA2  = pack2(0.075f,       0.075f);
    const ull CA3  = pack2(0.044642857f, 0.044642857f);
    const ull CA4  = pack2(0.030381944f, 0.030381944f);
    const ull NEGC = pack2(-7.2134752f,  -7.2134752f);
    const ull CPI  = pack2(22.6618023f,  22.6618023f);

    auto tpair = [&](ull x2, ull la2) -> float {
        ull u  = mul2(x2, x2);
        ull q  = fma2(CA4, u, CA3);
        q = fma2(q, u, CA2);
        q = fma2(q, u, CA1);
        ull xu = mul2(x2, u);
        ull p  = fma2(xu, q, x2);     // asin(x)
        ull t  = fma2(p, NEGC, CPI);
        ull z  = fma2(p, t, la2);     // -c*p^2 + c*pi*p + la'
        float z0, z1; unpack2(z, z0, z1);
        return ex2(z0) + ex2(z1);
    };

    float s0 = 0.0f, s1 = 0.0f;
    const float2* la_p = (const float2*)g_la;
    ull ipp[4];   // [E row g | E row g+8 | O row g | O row g+8]

    auto epiE = [&](int itp) {
        float2 laE = la_p[itp * 8 + t4];
        ull la2 = pack2(laE.x, laE.y);
        s0 += tpair(ipp[0], la2);
        s1 += tpair(ipp[1], la2);
    };
    auto epiO = [&](int itp) {
        float2 laO = la_p[itp * 8 + 4 + t4];
        ull la2 = pack2(laO.x, laO.y);
        s0 += tpair(ipp[2], la2);
        s1 += tpair(ipp[3], la2);
    };

    auto body = [&](int it, bool epi) {
        const uint4* pB = g_B + it * 256 + lane;
        // batch 1: ks0-3
        uint4 b0 = pB[0], b1 = pB[32], b2 = pB[64], b3 = pB[96];

        float Ea0=0,Ea1=0,Ea2=0,Ea3=0;   // E cols, ks0-3
        float Eb0=0,Eb1=0,Eb2=0,Eb3=0;   // E cols, ks4-7
        float Oa0=0,Oa1=0,Oa2=0,Oa3=0;   // O cols, ks0-3
        float Ob0=0,Ob1=0,Ob2=0,Ob3=0;   // O cols, ks4-7

        mma16816h(Ea0,Ea1,Ea2,Ea3, A[0].x,A[0].y,A[0].z,A[0].w, b0.x,b0.y);
        mma16816h(Oa0,Oa1,Oa2,Oa3, A[0].x,A[0].y,A[0].z,A[0].w, b0.z,b0.w);
        mma16816h(Ea0,Ea1,Ea2,Ea3, A[1].x,A[1].y,A[1].z,A[1].w, b1.x,b1.y);
        mma16816h(Oa0,Oa1,Oa2,Oa3, A[1].x,A[1].y,A[1].z,A[1].w, b1.z,b1.w);

        // batch 2 loads: covered by remaining chain-a MMAs + epiE
        uint4 b4 = pB[128], b5 = pB[160], b6 = pB[192], b7 = pB[224];

        mma16816h(Ea0,Ea1,Ea2,Ea3, A[2].x,A[2].y,A[2].z,A[2].w, b2.x,b2.y);
        mma16816h(Oa0,Oa1,Oa2,Oa3, A[2].x,A[2].y,A[2].z,A[2].w, b2.z,b2.w);
        mma16816h(Ea0,Ea1,Ea2,Ea3, A[3].x,A[3].y,A[3].z,A[3].w, b3.x,b3.y);
        mma16816h(Oa0,Oa1,Oa2,Oa3, A[3].x,A[3].y,A[3].z,A[3].w, b3.z,b3.w);

        if (epi) epiE(it - 1);

        mma16816h(Eb0,Eb1,Eb2,Eb3, A[4].x,A[4].y,A[4].z,A[4].w, b4.x,b4.y);
        mma16816h(Ob0,Ob1,Ob2,Ob3, A[4].x,A[4].y,A[4].z,A[4].w, b4.z,b4.w);
        mma16816h(Eb0,Eb1,Eb2,Eb3, A[5].x,A[5].y,A[5].z,A[5].w, b5.x,b5.y);
        mma16816h(Ob0,Ob1,Ob2,Ob3, A[5].x,A[5].y,A[5].z,A[5].w, b5.z,b5.w);
        mma16816h(Eb0,Eb1,Eb2,Eb3, A[6].x,A[6].y,A[6].z,A[6].w, b6.x,b6.y);
        mma16816h(Ob0,Ob1,Ob2,Ob3, A[6].x,A[6].y,A[6].z,A[6].w, b6.z,b6.w);
        mma16816h(Eb0,Eb1,Eb2,Eb3, A[7].x,A[7].y,A[7].z,A[7].w, b7.x,b7.y);
        mma16816h(Ob0,Ob1,Ob2,Ob3, A[7].x,A[7].y,A[7].z,A[7].w, b7.z,b7.w);

        if (epi) epiO(it - 1);

        ipp[0] = pack2(Ea0 + Eb0, Ea1 + Eb1);   // row g (E cols)
        ipp[1] = pack2(Ea2 + Eb2, Ea3 + Eb3);   // row g+8
        ipp[2] = pack2(Oa0 + Ob0, Oa1 + Ob1);
        ipp[3] = pack2(Oa2 + Ob2, Oa3 + Ob3);
    };

    body(first, false);                  // peeled prologue
#pragma unroll 1
    for (int it = first + 1; it < first + 32; it++)
        body(it, true);
    epiE(first + 31);                    // drain
    epiO(first + 31);

    // reduce across the 4 lanes sharing the same rows (t4 = 0..3)
    s0 += __shfl_xor_sync(0xffffffffu, s0, 1);
    s0 += __shfl_xor_sync(0xffffffffu, s0, 2);
    s1 += __shfl_xor_sync(0xffffffffu, s1, 1);
    s1 += __shfl_xor_sync(0xffffffffu, s1, 2);

    if (t4 == 0) {
        red[half][g]     = s0;
        red[half][g + 8] = s1;
    }
    __syncthreads();
    if (tid < 16) {
        float S = red[0][tid] + red[1][tid];
        out[strip * 16 + tid] = 0.1f * log1pf(1.0f / S);
    }
}

// ---------------- launch ----------------
extern "C" void kernel_launch(void* const* d_in, const int* in_sizes, int n_in,
                              void* d_out, int out_size) {
    const float* xs     = (const float*)d_in[0];
    const float* mus    = (const float*)d_in[1];
    const float* alphas = (const float*)d_in[2];
    float* out = (float*)d_out;

    int B = in_sizes[0] / DDIM;    // 65536

    prepFused<<<64, 256>>>(mus, alphas);      // one prep launch: norms + fragments
    main_kernel<<<B / 16, 64>>>(xs, out);     // 4096 blocks x 2 warps
}

// round 15
// speedup vs baseline: 1.3863x; 1.0696x over previous
#include <cuda_runtime.h>
#include <cuda_fp16.h>
#include <cstdint>

#define DDIM   128
#define KPROTO 1024
typedef unsigned int u32;
typedef unsigned long long ull;

// Static device storage (no allocation).
__device__ uint4 g_B [64 * 8 * 32];     // 256 KB: B-hi frags [nbpair][ks][lane] = {b0E,b1E,b0O,b1O}
__device__ float g_la [KPROTO];         // -10*log2e*alpha - c*pi^2/4

// ---------------- helpers ----------------
__device__ __forceinline__ u32 pack_h2(float a, float b) {
    __half2 t;
    t.x = __float2half_rn(a);
    t.y = __float2half_rn(b);
    return *reinterpret_cast<u32*>(&t);
}
__device__ __forceinline__ ull pack2(float lo, float hi) {
    ull r; asm("mov.b64 %0, {%1, %2};" : "=l"(r) : "f"(lo), "f"(hi)); return r;
}
__device__ __forceinline__ void unpack2(ull v, float& lo, float& hi) {
    asm("mov.b64 {%0, %1}, %2;" : "=f"(lo), "=f"(hi) : "l"(v));
}
__device__ __forceinline__ ull fma2(ull a, ull b, ull c) {
    ull d; asm("fma.rn.f32x2 %0, %1, %2, %3;" : "=l"(d) : "l"(a), "l"(b), "l"(c)); return d;
}
__device__ __forceinline__ ull mul2(ull a, ull b) {
    ull d; asm("mul.rn.f32x2 %0, %1, %2;" : "=l"(d) : "l"(a), "l"(b)); return d;
}
__device__ __forceinline__ float ex2(float x) {
    float r; asm("ex2.approx.f32 %0, %1;" : "=f"(r) : "f"(x)); return r;
}
__device__ __forceinline__ void mma16816h(float& d0, float& d1, float& d2, float& d3,
                                          u32 a0, u32 a1, u32 a2, u32 a3,
                                          u32 b0, u32 b1) {
    asm volatile(
        "mma.sync.aligned.m16n8k16.row.col.f32.f16.f16.f32 "
        "{%0,%1,%2,%3},{%4,%5,%6,%7},{%8,%9},{%0,%1,%2,%3};"
        : "+f"(d0), "+f"(d1), "+f"(d2), "+f"(d3)
        : "r"(a0), "r"(a1), "r"(a2), "r"(a3), "r"(b0), "r"(b1));
}

// ---------------- fused prep: per-block column norms + B fragment packing ----------------
__global__ void prepFused(const float* __restrict__ mus, const float* __restrict__ alphas) {
    __shared__ float s_part[256];
    __shared__ float s_inv[16];

    const int tid = threadIdx.x;
    const int np  = blockIdx.x;
    const int n0  = np * 16;

    {
        int c = tid & 15, p = tid >> 4;
        float s = 0.0f;
#pragma unroll
        for (int i = 0; i < 8; i++) {
            float v = mus[(p * 8 + i) * KPROTO + n0 + c];
            s = fmaf(v, v, s);
        }
        s_part[tid] = s;
    }
    __syncthreads();
    if (tid < 16) {
        float t = 0.0f;
#pragma unroll
        for (int j = 0; j < 16; j++) t += s_part[j * 16 + tid];
        s_inv[tid] = rsqrtf(t);
        g_la[n0 + tid] = fmaf(-14.4269504088896340f, alphas[n0 + tid], -17.7985387f);
    }
    __syncthreads();

    {
        int lane = tid & 31;
        int ks   = tid >> 5;
        int g    = lane >> 2;
        int t4   = lane & 3;
        int k0   = ks * 16 + 2 * t4;
        int nE   = n0 + g;
        int nO   = nE + 8;
        float iE = s_inv[g], iO = s_inv[g + 8];
        float e0 = mus[(k0 + 0) * KPROTO + nE] * iE;
        float e1 = mus[(k0 + 1) * KPROTO + nE] * iE;
        float e2 = mus[(k0 + 8) * KPROTO + nE] * iE;
        float e3 = mus[(k0 + 9) * KPROTO + nE] * iE;
        float o0 = mus[(k0 + 0) * KPROTO + nO] * iO;
        float o1 = mus[(k0 + 1) * KPROTO + nO] * iO;
        float o2 = mus[(k0 + 8) * KPROTO + nO] * iO;
        float o3 = mus[(k0 + 9) * KPROTO + nO] * iO;
        uint4 o;
        o.x = pack_h2(e0, e1);
        o.y = pack_h2(e2, e3);
        o.z = pack_h2(o0, o1);
        o.w = pack_h2(o2, o3);
        g_B[(np * 8 + ks) * 32 + lane] = o;
    }
}

// ---------------- main: 2 strips/warp, fused A-convert, 4x8 chains, in-block reduce ----
// Block = 64 thr = 2 warps sharing strips (2b, 2b+1) = 32 rows; warp half does
// nb-pairs [half*32, +32). B read once per 32 rows -> half the L1 traffic of R14.
__global__ __launch_bounds__(64, 8)
void main_kernel(const float* __restrict__ xs, float* __restrict__ out) {
    __shared__ float red[2][32];

    const int tid  = threadIdx.x;
    const int half = tid >> 5;
    const int lane = tid & 31;
    const int g    = lane >> 2;
    const int t4   = lane & 3;
    const int sid  = blockIdx.x;           // 0..2047
    const int row0 = sid * 32 + g;         // strip0 rows: row0, row0+8
    const int row1 = row0 + 16;            // strip1 rows: row1, row1+8
    const int first = half * 32;

    // A fragments for both strips: convert 32 xs rows to fp16 in registers
    uint4 A0[8], A1[8];
    {
        const float* x00 = xs + (size_t)row0 * DDIM;
        const float* x01 = xs + (size_t)(row0 + 8) * DDIM;
        const float* x10 = xs + (size_t)row1 * DDIM;
        const float* x11 = xs + (size_t)(row1 + 8) * DDIM;
#pragma unroll
        for (int ks = 0; ks < 8; ks++) {
            int c0 = ks * 16 + 2 * t4;
            float2 p00 = *(const float2*)(x00 + c0);
            float2 p01 = *(const float2*)(x00 + c0 + 8);
            float2 p10 = *(const float2*)(x01 + c0);
            float2 p11 = *(const float2*)(x01 + c0 + 8);
            A0[ks].x = pack_h2(p00.x, p00.y);
            A0[ks].y = pack_h2(p10.x, p10.y);
            A0[ks].z = pack_h2(p01.x, p01.y);
            A0[ks].w = pack_h2(p11.x, p11.y);
            float2 q00 = *(const float2*)(x10 + c0);
            float2 q01 = *(const float2*)(x10 + c0 + 8);
            float2 q10 = *(const float2*)(x11 + c0);
            float2 q11 = *(const float2*)(x11 + c0 + 8);
            A1[ks].x = pack_h2(q00.x, q00.y);
            A1[ks].y = pack_h2(q10.x, q10.y);
            A1[ks].z = pack_h2(q01.x, q01.y);
            A1[ks].w = pack_h2(q11.x, q11.y);
        }
    }

    // asin Taylor (odd, deg 9) + exponent-fold constants (packed)
    const ull CA1  = pack2(0.16666667f,  0.16666667f);
    const ull CA2  = pack2(0.075f,       0.075f);
    const ull CA3  = pack2(0.044642857f, 0.044642857f);
    const ull CA4  = pack2(0.030381944f, 0.030381944f);
    const ull NEGC = pack2(-7.2134752f,  -7.2134752f);
    const ull CPI  = pack2(22.6618023f,  22.6618023f);

    auto tpair = [&](ull x2, ull la2) -> float {
        ull u  = mul2(x2, x2);
        ull q  = fma2(CA4, u, CA3);
        q = fma2(q, u, CA2);
        q = fma2(q, u, CA1);
        ull xu = mul2(x2, u);
        ull p  = fma2(xu, q, x2);     // asin(x)
        ull t  = fma2(p, NEGC, CPI);
        ull z  = fma2(p, t, la2);     // -c*p^2 + c*pi*p + la'
        float z0, z1; unpack2(z, z0, z1);
        return ex2(z0) + ex2(z1);
    };

    float s0 = 0.0f, s1 = 0.0f, s2 = 0.0f, s3 = 0.0f;
    const float2* la_p = (const float2*)g_la;
    ull ipp[8];   // strip0: [E g | E g8 | O g | O g8], strip1: +4

    auto epi0 = [&](int itp) {
        float2 laE = la_p[itp * 8 + t4];
        float2 laO = la_p[itp * 8 + 4 + t4];
        ull laE2 = pack2(laE.x, laE.y), laO2 = pack2(laO.x, laO.y);
        s0 += tpair(ipp[0], laE2) + tpair(ipp[2], laO2);
        s1 += tpair(ipp[1], laE2) + tpair(ipp[3], laO2);
    };
    auto epi1 = [&](int itp) {
        float2 laE = la_p[itp * 8 + t4];
        float2 laO = la_p[itp * 8 + 4 + t4];
        ull laE2 = pack2(laE.x, laE.y), laO2 = pack2(laO.x, laO.y);
        s2 += tpair(ipp[4], laE2) + tpair(ipp[6], laO2);
        s3 += tpair(ipp[5], laE2) + tpair(ipp[7], laO2);
    };

    auto body = [&](int it, bool epi) {
        const uint4* pB = g_B + it * 256 + lane;
        uint4 b0 = pB[0], b1 = pB[32], b2 = pB[64], b3 = pB[96];

        float E00=0,E01=0,E02=0,E03=0;   // strip0 E
        float O00=0,O01=0,O02=0,O03=0;   // strip0 O
        float E10=0,E11=0,E12=0,E13=0;   // strip1 E
        float O10=0,O11=0,O12=0,O13=0;   // strip1 O

        // ks 0..3, 4 chains
        mma16816h(E00,E01,E02,E03, A0[0].x,A0[0].y,A0[0].z,A0[0].w, b0.x,b0.y);
        mma16816h(O00,O01,O02,O03, A0[0].x,A0[0].y,A0[0].z,A0[0].w, b0.z,b0.w);
        mma16816h(E10,E11,E12,E13, A1[0].x,A1[0].y,A1[0].z,A1[0].w, b0.x,b0.y);
        mma16816h(O10,O11,O12,O13, A1[0].x,A1[0].y,A1[0].z,A1[0].w, b0.z,b0.w);
        mma16816h(E00,E01,E02,E03, A0[1].x,A0[1].y,A0[1].z,A0[1].w, b1.x,b1.y);
        mma16816h(O00,O01,O02,O03, A0[1].x,A0[1].y,A0[1].z,A0[1].w, b1.z,b1.w);
        mma16816h(E10,E11,E12,E13, A1[1].x,A1[1].y,A1[1].z,A1[1].w, b1.x,b1.y);
        mma16816h(O10,O11,O12,O13, A1[1].x,A1[1].y,A1[1].z,A1[1].w, b1.z,b1.w);
        mma16816h(E00,E01,E02,E03, A0[2].x,A0[2].y,A0[2].z,A0[2].w, b2.x,b2.y);
        mma16816h(O00,O01,O02,O03, A0[2].x,A0[2].y,A0[2].z,A0[2].w, b2.z,b2.w);
        mma16816h(E10,E11,E12,E13, A1[2].x,A1[2].y,A1[2].z,A1[2].w, b2.x,b2.y);
        mma16816h(O10,O11,O12,O13, A1[2].x,A1[2].y,A1[2].z,A1[2].w, b2.z,b2.w);
        mma16816h(E00,E01,E02,E03, A0[3].x,A0[3].y,A0[3].z,A0[3].w, b3.x,b3.y);
        mma16816h(O00,O01,O02,O03, A0[3].x,A0[3].y,A0[3].z,A0[3].w, b3.z,b3.w);
        mma16816h(E10,E11,E12,E13, A1[3].x,A1[3].y,A1[3].z,A1[3].w, b3.x,b3.y);
        mma16816h(O10,O11,O12,O13, A1[3].x,A1[3].y,A1[3].z,A1[3].w, b3.z,b3.w);

        // back-half loads; covered by epi0 + remaining MMAs
        uint4 b4 = pB[128], b5 = pB[160], b6 = pB[192], b7 = pB[224];

        if (epi) epi0(it - 1);

        // ks 4..7
        mma16816h(E00,E01,E02,E03, A0[4].x,A0[4].y,A0[4].z,A0[4].w, b4.x,b4.y);
        mma16816h(O00,O01,O02,O03, A0[4].x,A0[4].y,A0[4].z,A0[4].w, b4.z,b4.w);
        mma16816h(E10,E11,E12,E13, A1[4].x,A1[4].y,A1[4].z,A1[4].w, b4.x,b4.y);
        mma16816h(O10,O11,O12,O13, A1[4].x,A1[4].y,A1[4].z,A1[4].w, b4.z,b4.w);
        mma16816h(E00,E01,E02,E03, A0[5].x,A0[5].y,A0[5].z,A0[5].w, b5.x,b5.y);
        mma16816h(O00,O01,O02,O03, A0[5].x,A0[5].y,A0[5].z,A0[5].w, b5.z,b5.w);
        mma16816h(E10,E11,E12,E13, A1[5].x,A1[5].y,A1[5].z,A1[5].w, b5.x,b5.y);
        mma16816h(O10,O11,O12,O13, A1[5].x,A1[5].y,A1[5].z,A1[5].w, b5.z,b5.w);
        mma16816h(E00,E01,E02,E03, A0[6].x,A0[6].y,A0[6].z,A0[6].w, b6.x,b6.y);
        mma16816h(O00,O01,O02,O03, A0[6].x,A0[6].y,A0[6].z,A0[6].w, b6.z,b6.w);
        mma16816h(E10,E11,E12,E13, A1[6].x,A1[6].y,A1[6].z,A1[6].w, b6.x,b6.y);
        mma16816h(O10,O11,O12,O13, A1[6].x,A1[6].y,A1[6].z,A1[6].w, b6.z,b6.w);
        mma16816h(E00,E01,E02,E03, A0[7].x,A0[7].y,A0[7].z,A0[7].w, b7.x,b7.y);
        mma16816h(O00,O01,O02,O03, A0[7].x,A0[7].y,A0[7].z,A0[7].w, b7.z,b7.w);
        mma16816h(E10,E11,E12,E13, A1[7].x,A1[7].y,A1[7].z,A1[7].w, b7.x,b7.y);
        mma16816h(O10,O11,O12,O13, A1[7].x,A1[7].y,A1[7].z,A1[7].w, b7.z,b7.w);

        if (epi) epi1(it - 1);

        ipp[0] = pack2(E00, E01);  ipp[1] = pack2(E02, E03);
        ipp[2] = pack2(O00, O01);  ipp[3] = pack2(O02, O03);
        ipp[4] = pack2(E10, E11);  ipp[5] = pack2(E12, E13);
        ipp[6] = pack2(O10, O11);  ipp[7] = pack2(O12, O13);
    };

    body(first, false);                  // peeled prologue
#pragma unroll 1
    for (int it = first + 1; it < first + 32; it++)
        body(it, true);
    epi0(first + 31);                    // drain
    epi1(first + 31);

    // reduce across the 4 lanes sharing the same rows (t4 = 0..3)
    s0 += __shfl_xor_sync(0xffffffffu, s0, 1);
    s0 += __shfl_xor_sync(0xffffffffu, s0, 2);
    s1 += __shfl_xor_sync(0xffffffffu, s1, 1);
    s1 += __shfl_xor_sync(0xffffffffu, s1, 2);
    s2 += __shfl_xor_sync(0xffffffffu, s2, 1);
    s2 += __shfl_xor_sync(0xffffffffu, s2, 2);
    s3 += __shfl_xor_sync(0xffffffffu, s3, 1);
    s3 += __shfl_xor_sync(0xffffffffu, s3, 2);

    if (t4 == 0) {
        red[half][g]      = s0;
        red[half][g + 8]  = s1;
        red[half][g + 16] = s2;
        red[half][g + 24] = s3;
    }
    __syncthreads();
    if (tid < 32) {
        float S = red[0][tid] + red[1][tid];
        out[sid * 32 + tid] = 0.1f * log1pf(1.0f / S);
    }
}

// ---------------- launch ----------------
extern "C" void kernel_launch(void* const* d_in, const int* in_sizes, int n_in,
                              void* d_out, int out_size) {
    const float* xs     = (const float*)d_in[0];
    const float* mus    = (const float*)d_in[1];
    const float* alphas = (const float*)d_in[2];
    float* out = (float*)d_out;

    int B = in_sizes[0] / DDIM;    // 65536

    prepFused<<<64, 256>>>(mus, alphas);      // one prep launch
    main_kernel<<<B / 32, 64>>>(xs, out);     // 2048 blocks x 2 warps
}